// round 1
// baseline (speedup 1.0000x reference)
#include <cuda_runtime.h>
#include <cuda_bf16.h>

// Problem constants
#define Bq    4
#define Tq    8192
#define Cq    1024
#define Hq    8
#define Dq    128
#define Mq    (Bq*Tq)          // 32768
#define BHq   (Bq*Hq)          // 32
#define ROWSq (Mq*Hq)          // 262144 rows of 128

// -------- device scratch (static, no allocation) --------
__device__ float g_q[Mq*Cq];
__device__ float g_k[Mq*Cq];
__device__ float g_v[Mq*Cq];
__device__ float g_yy[Mq*Cq];
__device__ float g_ctx[BHq*Dq*Dq];   // [bh][d][e]
__device__ float g_ksum[BHq*Dq];     // [bh][d]
__device__ float g_dinv[BHq*Tq];     // [bh][t]

// -------- zero the accumulated buffers (needed each graph replay) --------
__global__ void zero_kernel() {
    int i = blockIdx.x * blockDim.x + threadIdx.x;
    if (i < BHq*Dq*Dq) g_ctx[i] = 0.f;
    if (i < BHq*Dq)    g_ksum[i] = 0.f;
}

// -------- generic tiled GEMM:  C[M,N] = A[M,K] @ B[K,N] + bias  --------
// BM=BN=128, BK=16, 256 threads, 8x8 microtile, double buffered
__global__ __launch_bounds__(256, 2)
void gemm_bias_kernel(const float* __restrict__ A, const float* __restrict__ B,
                      const float* __restrict__ bias, float* __restrict__ C,
                      int K, int N)
{
    __shared__ float As[2][16][128];
    __shared__ float Bs[2][16][128];
    const int tid = threadIdx.x;
    const int m0 = blockIdx.y * 128;
    const int n0 = blockIdx.x * 128;
    const int tx = tid & 15;
    const int ty = tid >> 4;

    const int aRow = tid >> 2;          // 0..63
    const int aCol = (tid & 3) << 2;    // 0,4,8,12
    const int bRow = tid >> 5;          // 0..7
    const int bCol = (tid & 31) << 2;   // 0..124

    const float* Abase = A + (long)(m0 + aRow) * K + aCol;
    const float* Bbase = B + (long)bRow * N + n0 + bCol;

    float acc[8][8];
#pragma unroll
    for (int i = 0; i < 8; i++)
#pragma unroll
        for (int j = 0; j < 8; j++) acc[i][j] = 0.f;

    const int nk = K >> 4;
    float4 pa0, pa1, pb0, pb1;

    // prefetch tile 0
    pa0 = *(const float4*)(Abase);
    pa1 = *(const float4*)(Abase + 64L * K);
    pb0 = *(const float4*)(Bbase);
    pb1 = *(const float4*)(Bbase + 8L * N);
    // store into buffer 0 (A transposed)
    As[0][aCol+0][aRow]    = pa0.x; As[0][aCol+1][aRow]    = pa0.y;
    As[0][aCol+2][aRow]    = pa0.z; As[0][aCol+3][aRow]    = pa0.w;
    As[0][aCol+0][aRow+64] = pa1.x; As[0][aCol+1][aRow+64] = pa1.y;
    As[0][aCol+2][aRow+64] = pa1.z; As[0][aCol+3][aRow+64] = pa1.w;
    *(float4*)&Bs[0][bRow][bCol]   = pb0;
    *(float4*)&Bs[0][bRow+8][bCol] = pb1;
    __syncthreads();

    for (int kt = 0; kt < nk; kt++) {
        const int buf = kt & 1;
        if (kt + 1 < nk) {
            const int k0 = (kt + 1) << 4;
            pa0 = *(const float4*)(Abase + k0);
            pa1 = *(const float4*)(Abase + 64L * K + k0);
            pb0 = *(const float4*)(Bbase + (long)k0 * N);
            pb1 = *(const float4*)(Bbase + (long)(k0 + 8) * N);
        }
#pragma unroll
        for (int kk = 0; kk < 16; kk++) {
            float4 a0 = *(const float4*)&As[buf][kk][ty*8];
            float4 a1 = *(const float4*)&As[buf][kk][ty*8+4];
            float4 b0 = *(const float4*)&Bs[buf][kk][tx*8];
            float4 b1 = *(const float4*)&Bs[buf][kk][tx*8+4];
            float a[8] = {a0.x,a0.y,a0.z,a0.w,a1.x,a1.y,a1.z,a1.w};
            float b[8] = {b0.x,b0.y,b0.z,b0.w,b1.x,b1.y,b1.z,b1.w};
#pragma unroll
            for (int i = 0; i < 8; i++)
#pragma unroll
                for (int j = 0; j < 8; j++) acc[i][j] += a[i] * b[j];
        }
        if (kt + 1 < nk) {
            const int nb = buf ^ 1;
            As[nb][aCol+0][aRow]    = pa0.x; As[nb][aCol+1][aRow]    = pa0.y;
            As[nb][aCol+2][aRow]    = pa0.z; As[nb][aCol+3][aRow]    = pa0.w;
            As[nb][aCol+0][aRow+64] = pa1.x; As[nb][aCol+1][aRow+64] = pa1.y;
            As[nb][aCol+2][aRow+64] = pa1.z; As[nb][aCol+3][aRow+64] = pa1.w;
            *(float4*)&Bs[nb][bRow][bCol]   = pb0;
            *(float4*)&Bs[nb][bRow+8][bCol] = pb1;
        }
        __syncthreads();
    }

    float4 bb0 = *(const float4*)(bias + n0 + tx*8);
    float4 bb1 = *(const float4*)(bias + n0 + tx*8 + 4);
#pragma unroll
    for (int i = 0; i < 8; i++) {
        long row = m0 + ty*8 + i;
        float4 o0 = make_float4(acc[i][0]+bb0.x, acc[i][1]+bb0.y,
                                acc[i][2]+bb0.z, acc[i][3]+bb0.w);
        float4 o1 = make_float4(acc[i][4]+bb1.x, acc[i][5]+bb1.y,
                                acc[i][6]+bb1.z, acc[i][7]+bb1.w);
        *(float4*)(C + row*N + n0 + tx*8)     = o0;
        *(float4*)(C + row*N + n0 + tx*8 + 4) = o1;
    }
}

// -------- softmax over last dim (128), one warp per row, in place --------
__global__ void softmax_kernel(float* __restrict__ P, int nrows)
{
    int gw = (blockIdx.x * blockDim.x + threadIdx.x) >> 5;
    if (gw >= nrows) return;
    int lane = threadIdx.x & 31;
    float* p = P + (long)gw * 128 + lane * 4;
    float4 v = *(float4*)p;
    float mx = fmaxf(fmaxf(v.x, v.y), fmaxf(v.z, v.w));
#pragma unroll
    for (int o = 16; o; o >>= 1) mx = fmaxf(mx, __shfl_xor_sync(~0u, mx, o));
    v.x = expf(v.x - mx); v.y = expf(v.y - mx);
    v.z = expf(v.z - mx); v.w = expf(v.w - mx);
    float s = v.x + v.y + v.z + v.w;
#pragma unroll
    for (int o = 16; o; o >>= 1) s += __shfl_xor_sync(~0u, s, o);
    float inv = 1.f / s;
    v.x *= inv; v.y *= inv; v.z *= inv; v.w *= inv;
    *(float4*)p = v;
}

// -------- k_sum[b,h,d] = sum_t k[b,t,h,d] ; grid (BH, 16 chunks of 512 t) --------
__global__ void ksum_kernel()
{
    int bh = blockIdx.x;
    int b = bh >> 3, h = bh & 7;
    int t0 = blockIdx.y * 512;
    int d = threadIdx.x;
    const float* p = g_k + ((long)(b*Tq + t0)) * Cq + h*128 + d;
    float s = 0.f;
    for (int t = 0; t < 512; t++) s += p[(long)t * Cq];
    atomicAdd(&g_ksum[bh*128 + d], s);
}

// -------- D_inv[bh,t] = 1 / dot(q_row, ksum_row) ; one warp per row --------
__global__ void dinv_kernel()
{
    int gw = (blockIdx.x * blockDim.x + threadIdx.x) >> 5;
    if (gw >= ROWSq) return;
    int lane = threadIdx.x & 31;
    int h = gw & 7;
    int bt = gw >> 3;
    int t = bt & (Tq - 1);
    int b = bt >> 13;
    float4 qv = *(const float4*)(g_q + (long)gw * 128 + lane * 4);
    float4 kv = *(const float4*)(g_ksum + (b*Hq + h) * 128 + lane * 4);
    float s = qv.x*kv.x + qv.y*kv.y + qv.z*kv.z + qv.w*kv.w;
#pragma unroll
    for (int o = 16; o; o >>= 1) s += __shfl_xor_sync(~0u, s, o);
    if (!lane) g_dinv[(long)(b*Hq + h) * Tq + t] = 1.f / s;
}

// -------- context[bh,d,e] = sum_t k[t,d] * v[t,e]  (split-T with atomics) --------
__global__ __launch_bounds__(256, 2)
void ctx_kernel()
{
    __shared__ float As[2][16][128];
    __shared__ float Bs[2][16][128];
    const int bh = blockIdx.x;
    const int b = bh >> 3, h = bh & 7;
    const int t0 = blockIdx.y * 512;
    const int tid = threadIdx.x;
    const int tx = tid & 15, ty = tid >> 4;
    const int lRow = tid >> 5;          // 0..7
    const int lCol = (tid & 31) << 2;

    const float* kb = g_k + ((long)(b*Tq + t0 + lRow)) * Cq + h*128 + lCol;
    const float* vb = g_v + ((long)(b*Tq + t0 + lRow)) * Cq + h*128 + lCol;

    float acc[8][8];
#pragma unroll
    for (int i = 0; i < 8; i++)
#pragma unroll
        for (int j = 0; j < 8; j++) acc[i][j] = 0.f;

    float4 pa0, pa1, pb0, pb1;
    pa0 = *(const float4*)(kb);
    pa1 = *(const float4*)(kb + 8L*Cq);
    pb0 = *(const float4*)(vb);
    pb1 = *(const float4*)(vb + 8L*Cq);
    *(float4*)&As[0][lRow][lCol]   = pa0;
    *(float4*)&As[0][lRow+8][lCol] = pa1;
    *(float4*)&Bs[0][lRow][lCol]   = pb0;
    *(float4*)&Bs[0][lRow+8][lCol] = pb1;
    __syncthreads();

    const int nk = 32;  // 512 t / 16
    for (int kt = 0; kt < nk; kt++) {
        const int buf = kt & 1;
        if (kt + 1 < nk) {
            long off = (long)((kt + 1) * 16) * Cq;
            pa0 = *(const float4*)(kb + off);
            pa1 = *(const float4*)(kb + off + 8L*Cq);
            pb0 = *(const float4*)(vb + off);
            pb1 = *(const float4*)(vb + off + 8L*Cq);
        }
#pragma unroll
        for (int kk = 0; kk < 16; kk++) {
            float4 a0 = *(const float4*)&As[buf][kk][ty*8];
            float4 a1 = *(const float4*)&As[buf][kk][ty*8+4];
            float4 b0 = *(const float4*)&Bs[buf][kk][tx*8];
            float4 b1 = *(const float4*)&Bs[buf][kk][tx*8+4];
            float a[8] = {a0.x,a0.y,a0.z,a0.w,a1.x,a1.y,a1.z,a1.w};
            float b[8] = {b0.x,b0.y,b0.z,b0.w,b1.x,b1.y,b1.z,b1.w};
#pragma unroll
            for (int i = 0; i < 8; i++)
#pragma unroll
                for (int j = 0; j < 8; j++) acc[i][j] += a[i] * b[j];
        }
        if (kt + 1 < nk) {
            const int nb = buf ^ 1;
            *(float4*)&As[nb][lRow][lCol]   = pa0;
            *(float4*)&As[nb][lRow+8][lCol] = pa1;
            *(float4*)&Bs[nb][lRow][lCol]   = pb0;
            *(float4*)&Bs[nb][lRow+8][lCol] = pb1;
        }
        __syncthreads();
    }

    float* cbase = g_ctx + (long)bh * Dq * Dq;
#pragma unroll
    for (int i = 0; i < 8; i++)
#pragma unroll
        for (int j = 0; j < 8; j++)
            atomicAdd(&cbase[(ty*8 + i) * 128 + tx*8 + j], acc[i][j]);
}

// -------- y[t,e] = (sum_d q[t,d]*ctx[d,e]) * Dinv[t] + q[t,e]  --------
__global__ __launch_bounds__(256, 2)
void y_kernel()
{
    __shared__ float As[2][16][128];
    __shared__ float Bs[2][16][128];
    __shared__ float dinv_s[128];
    const int bh = blockIdx.x;
    const int b = bh >> 3, h = bh & 7;
    const int t0 = blockIdx.y * 128;
    const int tid = threadIdx.x;
    const int tx = tid & 15, ty = tid >> 4;

    if (tid < 128) dinv_s[tid] = g_dinv[(long)bh * Tq + t0 + tid];

    const int aRow = tid >> 2;          // 0..63
    const int aCol = (tid & 3) << 2;
    const int bRow = tid >> 5;          // 0..7
    const int bCol = (tid & 31) << 2;

    const float* qb = g_q + ((long)(b*Tq + t0 + aRow)) * Cq + h*128 + aCol;
    const float* cb = g_ctx + (long)bh * Dq * Dq + bRow * 128 + bCol;

    float acc[8][8];
#pragma unroll
    for (int i = 0; i < 8; i++)
#pragma unroll
        for (int j = 0; j < 8; j++) acc[i][j] = 0.f;

    float4 pa0, pa1, pb0, pb1;
    pa0 = *(const float4*)(qb);
    pa1 = *(const float4*)(qb + 64L*Cq);
    pb0 = *(const float4*)(cb);
    pb1 = *(const float4*)(cb + 8L*128);
    As[0][aCol+0][aRow]    = pa0.x; As[0][aCol+1][aRow]    = pa0.y;
    As[0][aCol+2][aRow]    = pa0.z; As[0][aCol+3][aRow]    = pa0.w;
    As[0][aCol+0][aRow+64] = pa1.x; As[0][aCol+1][aRow+64] = pa1.y;
    As[0][aCol+2][aRow+64] = pa1.z; As[0][aCol+3][aRow+64] = pa1.w;
    *(float4*)&Bs[0][bRow][bCol]   = pb0;
    *(float4*)&Bs[0][bRow+8][bCol] = pb1;
    __syncthreads();

    const int nk = 8;   // K = 128 / 16
    for (int kt = 0; kt < nk; kt++) {
        const int buf = kt & 1;
        if (kt + 1 < nk) {
            const int k0 = (kt + 1) << 4;
            pa0 = *(const float4*)(qb + k0);
            pa1 = *(const float4*)(qb + 64L*Cq + k0);
            pb0 = *(const float4*)(cb + k0 * 128);
            pb1 = *(const float4*)(cb + (k0 + 8) * 128);
        }
#pragma unroll
        for (int kk = 0; kk < 16; kk++) {
            float4 a0 = *(const float4*)&As[buf][kk][ty*8];
            float4 a1 = *(const float4*)&As[buf][kk][ty*8+4];
            float4 b0 = *(const float4*)&Bs[buf][kk][tx*8];
            float4 b1 = *(const float4*)&Bs[buf][kk][tx*8+4];
            float a[8] = {a0.x,a0.y,a0.z,a0.w,a1.x,a1.y,a1.z,a1.w};
            float b[8] = {b0.x,b0.y,b0.z,b0.w,b1.x,b1.y,b1.z,b1.w};
#pragma unroll
            for (int i = 0; i < 8; i++)
#pragma unroll
                for (int j = 0; j < 8; j++) acc[i][j] += a[i] * b[j];
        }
        if (kt + 1 < nk) {
            const int nb = buf ^ 1;
            As[nb][aCol+0][aRow]    = pa0.x; As[nb][aCol+1][aRow]    = pa0.y;
            As[nb][aCol+2][aRow]    = pa0.z; As[nb][aCol+3][aRow]    = pa0.w;
            As[nb][aCol+0][aRow+64] = pa1.x; As[nb][aCol+1][aRow+64] = pa1.y;
            As[nb][aCol+2][aRow+64] = pa1.z; As[nb][aCol+3][aRow+64] = pa1.w;
            *(float4*)&Bs[nb][bRow][bCol]   = pb0;
            *(float4*)&Bs[nb][bRow+8][bCol] = pb1;
        }
        __syncthreads();
    }

#pragma unroll
    for (int i = 0; i < 8; i++) {
        int m = ty*8 + i;
        float dv = dinv_s[m];
        long gi = ((long)(b*Tq + t0 + m)) * Cq + h*128 + tx*8;
        float4 q0 = *(const float4*)(g_q + gi);
        float4 q1 = *(const float4*)(g_q + gi + 4);
        float4 o0 = make_float4(acc[i][0]*dv + q0.x, acc[i][1]*dv + q0.y,
                                acc[i][2]*dv + q0.z, acc[i][3]*dv + q0.w);
        float4 o1 = make_float4(acc[i][4]*dv + q1.x, acc[i][5]*dv + q1.y,
                                acc[i][6]*dv + q1.z, acc[i][7]*dv + q1.w);
        *(float4*)(g_yy + gi)     = o0;
        *(float4*)(g_yy + gi + 4) = o1;
    }
}

// ---------------------------------------------------------------------------
extern "C" void kernel_launch(void* const* d_in, const int* in_sizes, int n_in,
                              void* d_out, int out_size)
{
    const float* x  = (const float*)d_in[0];
    const float* Wq = (const float*)d_in[1];
    const float* bq = (const float*)d_in[2];
    const float* Wk = (const float*)d_in[3];
    const float* bk = (const float*)d_in[4];
    const float* Wv = (const float*)d_in[5];
    const float* bv = (const float*)d_in[6];
    const float* Wp = (const float*)d_in[7];
    const float* bp = (const float*)d_in[8];
    float* out = (float*)d_out;

    float *pq, *pk, *pv, *pyy;
    cudaGetSymbolAddress((void**)&pq,  g_q);
    cudaGetSymbolAddress((void**)&pk,  g_k);
    cudaGetSymbolAddress((void**)&pv,  g_v);
    cudaGetSymbolAddress((void**)&pyy, g_yy);

    zero_kernel<<<2048, 256>>>();

    dim3 gg(Cq/128, Mq/128);   // (8, 256)
    gemm_bias_kernel<<<gg, 256>>>(x, Wq, bq, pq, Cq, Cq);
    gemm_bias_kernel<<<gg, 256>>>(x, Wk, bk, pk, Cq, Cq);
    gemm_bias_kernel<<<gg, 256>>>(x, Wv, bv, pv, Cq, Cq);

    // softmax over head dim for q and k (in place); 8 warps per block
    softmax_kernel<<<ROWSq/8, 256>>>(pq, ROWSq);
    softmax_kernel<<<ROWSq/8, 256>>>(pk, ROWSq);

    ksum_kernel<<<dim3(BHq, 16), 128>>>();
    dinv_kernel<<<ROWSq/8, 256>>>();
    ctx_kernel<<<dim3(BHq, 16), 256>>>();
    y_kernel<<<dim3(BHq, Tq/128), 256>>>();

    gemm_bias_kernel<<<gg, 256>>>(pyy, Wp, bp, out, Cq, Cq);
}

// round 3
// speedup vs baseline: 2.3080x; 2.3080x over previous
#include <cuda_runtime.h>
#include <cuda_bf16.h>
#include <cstdint>

// Problem constants
#define Bq    4
#define Tq    8192
#define Cq    1024
#define Hq    8
#define Dq    128
#define Mq    (Bq*Tq)          // 32768
#define BHq   (Bq*Hq)          // 32
#define ROWSq (Mq*Hq)          // 262144 rows of 128
#define KSP   3072             // split-K' = 3*1024

// ---------------- device scratch (static, no allocation) ----------------
__device__ __nv_bfloat16 g_xs[(long)Mq*KSP];   // x split   [m][k']  192MB
__device__ __nv_bfloat16 g_ys[(long)Mq*KSP];   // y split   [m][k']  192MB
__device__ __nv_bfloat16 g_wq[1024*KSP];       // W^T split [n][k']  6MB
__device__ __nv_bfloat16 g_wk[1024*KSP];
__device__ __nv_bfloat16 g_wv[1024*KSP];
__device__ __nv_bfloat16 g_wp[1024*KSP];
__device__ float g_q[(long)Mq*Cq];
__device__ float g_k[(long)Mq*Cq];
__device__ float g_v[(long)Mq*Cq];
__device__ float g_yy[(long)Mq*Cq];
__device__ float g_ctx[BHq*Dq*Dq];
__device__ float g_ksum[BHq*Dq];
__device__ float g_dinv[BHq*Tq];

// ---------------- PTX helpers (arch-generic, sm_80+) ----------------
__device__ __forceinline__ uint32_t smem_to_u32(const void* p) {
    uint32_t a;
    asm("{ .reg .u64 t; cvta.to.shared.u64 t, %1; cvt.u32.u64 %0, t; }" : "=r"(a) : "l"(p));
    return a;
}
#define CP_ASYNC16(dst, src) \
    asm volatile("cp.async.cg.shared.global [%0], [%1], 16;" :: "r"(dst), "l"(src))
#define CP_COMMIT() asm volatile("cp.async.commit_group;" ::: "memory")
#define CP_WAIT(n)  asm volatile("cp.async.wait_group %0;" :: "n"(n) : "memory")

__device__ __forceinline__ void ldm_x4(uint32_t& r0, uint32_t& r1, uint32_t& r2, uint32_t& r3,
                                       uint32_t a) {
    asm volatile("ldmatrix.sync.aligned.m8n8.x4.shared.b16 {%0,%1,%2,%3}, [%4];"
                 : "=r"(r0), "=r"(r1), "=r"(r2), "=r"(r3) : "r"(a));
}
__device__ __forceinline__ void mma16816(float* c, uint32_t a0, uint32_t a1, uint32_t a2,
                                         uint32_t a3, uint32_t b0, uint32_t b1) {
    asm volatile(
        "mma.sync.aligned.m16n8k16.row.col.f32.bf16.bf16.f32 "
        "{%0,%1,%2,%3}, {%4,%5,%6,%7}, {%8,%9}, {%0,%1,%2,%3};"
        : "+f"(c[0]), "+f"(c[1]), "+f"(c[2]), "+f"(c[3])
        : "r"(a0), "r"(a1), "r"(a2), "r"(a3), "r"(b0), "r"(b1));
}

// GEMM tiling
#define BKq   64
#define AST   72                 // smem row stride in bf16 (pad 64 -> 72, conflict-free)
#define ASTB  144                // bytes
#define TILEB (128*ASTB)         // 18432 bytes per tile buffer
#define NKCH  (KSP/BKq)          // 48 k-chunks
#define GEMM_SMEM (4*TILEB)      // 73728

// load one 128x64 bf16 tile (rows stride KSP in gmem) into smem via cp.async
__device__ __forceinline__ void load_tile(uint32_t sdst, const __nv_bfloat16* g, int tid) {
#pragma unroll
    for (int i = 0; i < 4; i++) {
        int idx = tid + i * 256;
        int row = idx >> 3, seg = idx & 7;
        uint32_t d = sdst + row * ASTB + seg * 16;
        const char* s = (const char*)(g + (long)row * KSP) + seg * 16;
        CP_ASYNC16(d, s);
    }
}

// C[m0:+128, n0:+128] = A[m0:,:K'] @ Bw[n0:,:K']^T + bias
__device__ void gemm128(const __nv_bfloat16* __restrict__ A,
                        const __nv_bfloat16* __restrict__ Bw,
                        const float* __restrict__ bias, float* __restrict__ C,
                        int m0, int n0)
{
    extern __shared__ char smem[];
    const uint32_t sb = smem_to_u32(smem);
    const int tid = threadIdx.x, lane = tid & 31, wid = tid >> 5;
    const int wm = wid & 1;     // 0..1  -> 64-row slab
    const int wn = wid >> 1;    // 0..3  -> 32-col slab

    float acc[4][4][4];
#pragma unroll
    for (int i = 0; i < 4; i++)
#pragma unroll
        for (int j = 0; j < 4; j++)
#pragma unroll
            for (int r = 0; r < 4; r++) acc[i][j][r] = 0.f;

    const uint32_t aB[2] = { sb,             sb + TILEB     };
    const uint32_t bB[2] = { sb + 2*TILEB,   sb + 3*TILEB   };
    const __nv_bfloat16* Ab = A + (long)m0 * KSP;
    const __nv_bfloat16* Bb = Bw + (long)n0 * KSP;

    load_tile(aB[0], Ab, tid);
    load_tile(bB[0], Bb, tid);
    CP_COMMIT();

    // per-thread ldmatrix offsets
    const uint32_t aoff = (uint32_t)((wm*64 + (lane & 7) + ((lane >> 3) & 1) * 8) * ASTB
                                     + ((lane >> 4) * 8) * 2);
    const uint32_t boff = (uint32_t)((wn*32 + (lane & 7) + (lane >> 4) * 8) * ASTB
                                     + (((lane >> 3) & 1) * 8) * 2);

    for (int c = 0; c < NKCH; c++) {
        const int buf = c & 1;
        if (c + 1 < NKCH) {
            load_tile(aB[buf ^ 1], Ab + (c + 1) * BKq, tid);
            load_tile(bB[buf ^ 1], Bb + (c + 1) * BKq, tid);
            CP_COMMIT();
            CP_WAIT(1);
        } else {
            CP_WAIT(0);
        }
        __syncthreads();

#pragma unroll
        for (int kk = 0; kk < 4; kk++) {
            uint32_t a[4][4], b[2][4];
#pragma unroll
            for (int mi = 0; mi < 4; mi++)
                ldm_x4(a[mi][0], a[mi][1], a[mi][2], a[mi][3],
                       aB[buf] + aoff + mi * 16 * ASTB + kk * 32);
#pragma unroll
            for (int nf = 0; nf < 2; nf++)
                ldm_x4(b[nf][0], b[nf][1], b[nf][2], b[nf][3],
                       bB[buf] + boff + nf * 16 * ASTB + kk * 32);
#pragma unroll
            for (int mi = 0; mi < 4; mi++)
#pragma unroll
                for (int ni = 0; ni < 4; ni++)
                    mma16816(acc[mi][ni], a[mi][0], a[mi][1], a[mi][2], a[mi][3],
                             b[ni >> 1][(ni & 1) * 2], b[ni >> 1][(ni & 1) * 2 + 1]);
        }
        __syncthreads();
    }

    // epilogue
    const int r0 = wm * 64 + (lane >> 2);
    const int c0 = wn * 32 + (lane & 3) * 2;
#pragma unroll
    for (int mi = 0; mi < 4; mi++)
#pragma unroll
        for (int ni = 0; ni < 4; ni++) {
            int row = r0 + mi * 16;
            int col = c0 + ni * 8;
            float bx = bias[n0 + col], by = bias[n0 + col + 1];
            float2 o0 = make_float2(acc[mi][ni][0] + bx, acc[mi][ni][1] + by);
            float2 o1 = make_float2(acc[mi][ni][2] + bx, acc[mi][ni][3] + by);
            *(float2*)(C + (long)(m0 + row) * 1024 + n0 + col) = o0;
            *(float2*)(C + (long)(m0 + row + 8) * 1024 + n0 + col) = o1;
        }
}

// QKV fused: blockIdx.x in [0,24): sel = x>>3, ntile = x&7 (A-tile shared via L2)
__global__ __launch_bounds__(256, 2)
void qkv_gemm_kernel(const float* bq, const float* bk, const float* bv)
{
    const int sel = blockIdx.x >> 3;
    const int n0 = (blockIdx.x & 7) * 128;
    const int m0 = blockIdx.y * 128;
    const __nv_bfloat16* W = (sel == 0) ? g_wq : (sel == 1) ? g_wk : g_wv;
    const float* bias      = (sel == 0) ? bq  : (sel == 1) ? bk  : bv;
    float* C               = (sel == 0) ? g_q : (sel == 1) ? g_k : g_v;
    gemm128(g_xs, W, bias, C, m0, n0);
}

__global__ __launch_bounds__(256, 2)
void proj_gemm_kernel(const float* bp, float* out)
{
    gemm128(g_ys, g_wp, bp, out, blockIdx.y * 128, blockIdx.x * 128);
}

// ---------------- conversion kernels ----------------
// A' = [hi | lo | hi] along K'  (pairs with B' = [hi | hi | lo])
__global__ void convert_a_kernel(const float* __restrict__ X, __nv_bfloat16* __restrict__ O)
{
    long gid = (long)blockIdx.x * blockDim.x + threadIdx.x;
    long i = gid * 4;
    long m = i >> 10;
    int  k = (int)(i & 1023);
    float4 v = *(const float4*)(X + i);
    __nv_bfloat16 h[4], l[4];
    float vv[4] = {v.x, v.y, v.z, v.w};
#pragma unroll
    for (int j = 0; j < 4; j++) {
        h[j] = __float2bfloat16(vv[j]);
        l[j] = __float2bfloat16(vv[j] - __bfloat162float(h[j]));
    }
    __nv_bfloat16* base = O + m * KSP;
    *(uint2*)(base + k)        = *(uint2*)h;
    *(uint2*)(base + 1024 + k) = *(uint2*)l;
    *(uint2*)(base + 2048 + k) = *(uint2*)h;
}

// W [K=1024][N=1024] -> O [n][k'=3072] transposed split: [hi | hi | lo]
__global__ void convert_w_kernel(const float* __restrict__ W, __nv_bfloat16* __restrict__ O)
{
    __shared__ float tile[32][33];
    const int n0 = blockIdx.x * 32, k0 = blockIdx.y * 32;
    const int tx = threadIdx.x & 31, ty = threadIdx.x >> 5;   // ty 0..7
#pragma unroll
    for (int r = 0; r < 32; r += 8)
        tile[ty + r][tx] = W[(long)(k0 + ty + r) * 1024 + n0 + tx];
    __syncthreads();
#pragma unroll
    for (int r = 0; r < 32; r += 8) {
        const int n = n0 + ty + r;
        float v = tile[tx][ty + r];
        __nv_bfloat16 hi = __float2bfloat16(v);
        __nv_bfloat16 lo = __float2bfloat16(v - __bfloat162float(hi));
        __nv_bfloat16* base = O + (long)n * KSP + k0 + tx;
        base[0]    = hi;
        base[1024] = hi;
        base[2048] = lo;
    }
}

// ---------------- zero accumulators ----------------
__global__ void zero_kernel() {
    int i = blockIdx.x * blockDim.x + threadIdx.x;
    if (i < BHq*Dq*Dq) g_ctx[i] = 0.f;
    if (i < BHq*Dq)    g_ksum[i] = 0.f;
}

// ---------------- softmax over last dim (128), warp per row ----------------
__global__ void softmax_kernel(float* __restrict__ P, int nrows)
{
    int gw = (blockIdx.x * blockDim.x + threadIdx.x) >> 5;
    if (gw >= nrows) return;
    int lane = threadIdx.x & 31;
    float* p = P + (long)gw * 128 + lane * 4;
    float4 v = *(float4*)p;
    float mx = fmaxf(fmaxf(v.x, v.y), fmaxf(v.z, v.w));
#pragma unroll
    for (int o = 16; o; o >>= 1) mx = fmaxf(mx, __shfl_xor_sync(~0u, mx, o));
    v.x = expf(v.x - mx); v.y = expf(v.y - mx);
    v.z = expf(v.z - mx); v.w = expf(v.w - mx);
    float s = v.x + v.y + v.z + v.w;
#pragma unroll
    for (int o = 16; o; o >>= 1) s += __shfl_xor_sync(~0u, s, o);
    float inv = 1.f / s;
    v.x *= inv; v.y *= inv; v.z *= inv; v.w *= inv;
    *(float4*)p = v;
}

// ---------------- k_sum ----------------
__global__ void ksum_kernel()
{
    int bh = blockIdx.x;
    int b = bh >> 3, h = bh & 7;
    int t0 = blockIdx.y * 512;
    int d = threadIdx.x;
    const float* p = g_k + ((long)(b*Tq + t0)) * Cq + h*128 + d;
    float s = 0.f;
    for (int t = 0; t < 512; t++) s += p[(long)t * Cq];
    atomicAdd(&g_ksum[bh*128 + d], s);
}

// ---------------- D_inv ----------------
__global__ void dinv_kernel()
{
    int gw = (blockIdx.x * blockDim.x + threadIdx.x) >> 5;
    if (gw >= ROWSq) return;
    int lane = threadIdx.x & 31;
    int h = gw & 7;
    int bt = gw >> 3;
    int t = bt & (Tq - 1);
    int b = bt >> 13;
    float4 qv = *(const float4*)(g_q + (long)gw * 128 + lane * 4);
    float4 kv = *(const float4*)(g_ksum + (b*Hq + h) * 128 + lane * 4);
    float s = qv.x*kv.x + qv.y*kv.y + qv.z*kv.z + qv.w*kv.w;
#pragma unroll
    for (int o = 16; o; o >>= 1) s += __shfl_xor_sync(~0u, s, o);
    if (!lane) g_dinv[(long)(b*Hq + h) * Tq + t] = 1.f / s;
}

// ---------------- context = K^T V (split-T, atomics) ----------------
__global__ __launch_bounds__(256, 2)
void ctx_kernel()
{
    __shared__ float As[2][16][128];
    __shared__ float Bs[2][16][128];
    const int bh = blockIdx.x;
    const int b = bh >> 3, h = bh & 7;
    const int t0 = blockIdx.y * 512;
    const int tid = threadIdx.x;
    const int tx = tid & 15, ty = tid >> 4;
    const int lRow = tid >> 5;
    const int lCol = (tid & 31) << 2;

    const float* kb = g_k + ((long)(b*Tq + t0 + lRow)) * Cq + h*128 + lCol;
    const float* vb = g_v + ((long)(b*Tq + t0 + lRow)) * Cq + h*128 + lCol;

    float acc[8][8];
#pragma unroll
    for (int i = 0; i < 8; i++)
#pragma unroll
        for (int j = 0; j < 8; j++) acc[i][j] = 0.f;

    float4 pa0, pa1, pb0, pb1;
    pa0 = *(const float4*)(kb);
    pa1 = *(const float4*)(kb + 8L*Cq);
    pb0 = *(const float4*)(vb);
    pb1 = *(const float4*)(vb + 8L*Cq);
    *(float4*)&As[0][lRow][lCol]   = pa0;
    *(float4*)&As[0][lRow+8][lCol] = pa1;
    *(float4*)&Bs[0][lRow][lCol]   = pb0;
    *(float4*)&Bs[0][lRow+8][lCol] = pb1;
    __syncthreads();

    const int nk = 32;
    for (int kt = 0; kt < nk; kt++) {
        const int buf = kt & 1;
        if (kt + 1 < nk) {
            long off = (long)((kt + 1) * 16) * Cq;
            pa0 = *(const float4*)(kb + off);
            pa1 = *(const float4*)(kb + off + 8L*Cq);
            pb0 = *(const float4*)(vb + off);
            pb1 = *(const float4*)(vb + off + 8L*Cq);
        }
#pragma unroll
        for (int kk = 0; kk < 16; kk++) {
            float4 a0 = *(const float4*)&As[buf][kk][ty*8];
            float4 a1 = *(const float4*)&As[buf][kk][ty*8+4];
            float4 b0 = *(const float4*)&Bs[buf][kk][tx*8];
            float4 b1 = *(const float4*)&Bs[buf][kk][tx*8+4];
            float a[8] = {a0.x,a0.y,a0.z,a0.w,a1.x,a1.y,a1.z,a1.w};
            float bb[8] = {b0.x,b0.y,b0.z,b0.w,b1.x,b1.y,b1.z,b1.w};
#pragma unroll
            for (int i = 0; i < 8; i++)
#pragma unroll
                for (int j = 0; j < 8; j++) acc[i][j] += a[i] * bb[j];
        }
        if (kt + 1 < nk) {
            const int nb = buf ^ 1;
            *(float4*)&As[nb][lRow][lCol]   = pa0;
            *(float4*)&As[nb][lRow+8][lCol] = pa1;
            *(float4*)&Bs[nb][lRow][lCol]   = pb0;
            *(float4*)&Bs[nb][lRow+8][lCol] = pb1;
        }
        __syncthreads();
    }

    float* cbase = g_ctx + (long)bh * Dq * Dq;
#pragma unroll
    for (int i = 0; i < 8; i++)
#pragma unroll
        for (int j = 0; j < 8; j++)
            atomicAdd(&cbase[(ty*8 + i) * 128 + tx*8 + j], acc[i][j]);
}

// ---------------- y = (q @ ctx) * Dinv + q ----------------
__global__ __launch_bounds__(256, 2)
void y_kernel()
{
    __shared__ float As[2][16][128];
    __shared__ float Bs[2][16][128];
    __shared__ float dinv_s[128];
    const int bh = blockIdx.x;
    const int b = bh >> 3, h = bh & 7;
    const int t0 = blockIdx.y * 128;
    const int tid = threadIdx.x;
    const int tx = tid & 15, ty = tid >> 4;

    if (tid < 128) dinv_s[tid] = g_dinv[(long)bh * Tq + t0 + tid];

    const int aRow = tid >> 2;
    const int aCol = (tid & 3) << 2;
    const int bRow = tid >> 5;
    const int bCol = (tid & 31) << 2;

    const float* qb = g_q + ((long)(b*Tq + t0 + aRow)) * Cq + h*128 + aCol;
    const float* cb = g_ctx + (long)bh * Dq * Dq + bRow * 128 + bCol;

    float acc[8][8];
#pragma unroll
    for (int i = 0; i < 8; i++)
#pragma unroll
        for (int j = 0; j < 8; j++) acc[i][j] = 0.f;

    float4 pa0, pa1, pb0, pb1;
    pa0 = *(const float4*)(qb);
    pa1 = *(const float4*)(qb + 64L*Cq);
    pb0 = *(const float4*)(cb);
    pb1 = *(const float4*)(cb + 8L*128);
    As[0][aCol+0][aRow]    = pa0.x; As[0][aCol+1][aRow]    = pa0.y;
    As[0][aCol+2][aRow]    = pa0.z; As[0][aCol+3][aRow]    = pa0.w;
    As[0][aCol+0][aRow+64] = pa1.x; As[0][aCol+1][aRow+64] = pa1.y;
    As[0][aCol+2][aRow+64] = pa1.z; As[0][aCol+3][aRow+64] = pa1.w;
    *(float4*)&Bs[0][bRow][bCol]   = pb0;
    *(float4*)&Bs[0][bRow+8][bCol] = pb1;
    __syncthreads();

    const int nk = 8;
    for (int kt = 0; kt < nk; kt++) {
        const int buf = kt & 1;
        if (kt + 1 < nk) {
            const int k0 = (kt + 1) << 4;
            pa0 = *(const float4*)(qb + k0);
            pa1 = *(const float4*)(qb + 64L*Cq + k0);
            pb0 = *(const float4*)(cb + k0 * 128);
            pb1 = *(const float4*)(cb + (k0 + 8) * 128);
        }
#pragma unroll
        for (int kk = 0; kk < 16; kk++) {
            float4 a0 = *(const float4*)&As[buf][kk][ty*8];
            float4 a1 = *(const float4*)&As[buf][kk][ty*8+4];
            float4 b0 = *(const float4*)&Bs[buf][kk][tx*8];
            float4 b1 = *(const float4*)&Bs[buf][kk][tx*8+4];
            float a[8] = {a0.x,a0.y,a0.z,a0.w,a1.x,a1.y,a1.z,a1.w};
            float bb[8] = {b0.x,b0.y,b0.z,b0.w,b1.x,b1.y,b1.z,b1.w};
#pragma unroll
            for (int i = 0; i < 8; i++)
#pragma unroll
                for (int j = 0; j < 8; j++) acc[i][j] += a[i] * bb[j];
        }
        if (kt + 1 < nk) {
            const int nb = buf ^ 1;
            As[nb][aCol+0][aRow]    = pa0.x; As[nb][aCol+1][aRow]    = pa0.y;
            As[nb][aCol+2][aRow]    = pa0.z; As[nb][aCol+3][aRow]    = pa0.w;
            As[nb][aCol+0][aRow+64] = pa1.x; As[nb][aCol+1][aRow+64] = pa1.y;
            As[nb][aCol+2][aRow+64] = pa1.z; As[nb][aCol+3][aRow+64] = pa1.w;
            *(float4*)&Bs[nb][bRow][bCol]   = pb0;
            *(float4*)&Bs[nb][bRow+8][bCol] = pb1;
        }
        __syncthreads();
    }

#pragma unroll
    for (int i = 0; i < 8; i++) {
        int m = ty*8 + i;
        float dv = dinv_s[m];
        long gi = ((long)(b*Tq + t0 + m)) * Cq + h*128 + tx*8;
        float4 q0 = *(const float4*)(g_q + gi);
        float4 q1 = *(const float4*)(g_q + gi + 4);
        float4 o0 = make_float4(acc[i][0]*dv + q0.x, acc[i][1]*dv + q0.y,
                                acc[i][2]*dv + q0.z, acc[i][3]*dv + q0.w);
        float4 o1 = make_float4(acc[i][4]*dv + q1.x, acc[i][5]*dv + q1.y,
                                acc[i][6]*dv + q1.z, acc[i][7]*dv + q1.w);
        *(float4*)(g_yy + gi)     = o0;
        *(float4*)(g_yy + gi + 4) = o1;
    }
}

// ---------------------------------------------------------------------------
extern "C" void kernel_launch(void* const* d_in, const int* in_sizes, int n_in,
                              void* d_out, int out_size)
{
    const float* x  = (const float*)d_in[0];
    const float* Wq = (const float*)d_in[1];
    const float* bq = (const float*)d_in[2];
    const float* Wk = (const float*)d_in[3];
    const float* bk = (const float*)d_in[4];
    const float* Wv = (const float*)d_in[5];
    const float* bv = (const float*)d_in[6];
    const float* Wp = (const float*)d_in[7];
    const float* bp = (const float*)d_in[8];
    float* out = (float*)d_out;

    float *pq, *pk, *pyy;
    __nv_bfloat16 *pxs, *pys, *pwq, *pwk, *pwv, *pwp;
    cudaGetSymbolAddress((void**)&pq,  g_q);
    cudaGetSymbolAddress((void**)&pk,  g_k);
    cudaGetSymbolAddress((void**)&pyy, g_yy);
    cudaGetSymbolAddress((void**)&pxs, g_xs);
    cudaGetSymbolAddress((void**)&pys, g_ys);
    cudaGetSymbolAddress((void**)&pwq, g_wq);
    cudaGetSymbolAddress((void**)&pwk, g_wk);
    cudaGetSymbolAddress((void**)&pwv, g_wv);
    cudaGetSymbolAddress((void**)&pwp, g_wp);

    cudaFuncSetAttribute(qkv_gemm_kernel,  cudaFuncAttributeMaxDynamicSharedMemorySize, GEMM_SMEM);
    cudaFuncSetAttribute(proj_gemm_kernel, cudaFuncAttributeMaxDynamicSharedMemorySize, GEMM_SMEM);

    zero_kernel<<<2048, 256>>>();

    convert_a_kernel<<<Mq*Cq/4/256, 256>>>(x, pxs);
    convert_w_kernel<<<dim3(32,32), 256>>>(Wq, pwq);
    convert_w_kernel<<<dim3(32,32), 256>>>(Wk, pwk);
    convert_w_kernel<<<dim3(32,32), 256>>>(Wv, pwv);
    convert_w_kernel<<<dim3(32,32), 256>>>(Wp, pwp);

    qkv_gemm_kernel<<<dim3(24, Mq/128), 256, GEMM_SMEM>>>(bq, bk, bv);

    softmax_kernel<<<ROWSq/8, 256>>>(pq, ROWSq);
    softmax_kernel<<<ROWSq/8, 256>>>(pk, ROWSq);

    ksum_kernel<<<dim3(BHq, 16), 128>>>();
    dinv_kernel<<<ROWSq/8, 256>>>();
    ctx_kernel<<<dim3(BHq, 16), 256>>>();
    y_kernel<<<dim3(BHq, Tq/128), 256>>>();

    convert_a_kernel<<<Mq*Cq/4/256, 256>>>(pyy, pys);
    proj_gemm_kernel<<<dim3(8, Mq/128), 256, GEMM_SMEM>>>(bp, out);
}

// round 4
// speedup vs baseline: 3.0591x; 1.3254x over previous
#include <cuda_runtime.h>
#include <cuda_fp16.h>
#include <cstdint>

// Problem constants
#define Bq    4
#define Tq    8192
#define Cq    1024
#define Hq    8
#define Dq    128
#define Mq    (Bq*Tq)          // 32768
#define BHq   (Bq*Hq)          // 32
#define ROWSq (Mq*Hq)          // 262144 rows of 128
#define KSP   2048             // split-K' = 2*1024 (fp16 2-term)

// ---------------- device scratch (static, no allocation) ----------------
__device__ __half g_xs[(long)Mq*KSP];   // x split   [m][k']  128MB
__device__ __half g_ys[(long)Mq*KSP];   // y split   [m][k']  128MB
__device__ __half g_wq[1024*KSP];       // W^T split [n][k']  4MB
__device__ __half g_wk[1024*KSP];
__device__ __half g_wv[1024*KSP];
__device__ __half g_wp[1024*KSP];
__device__ float g_q[(long)Mq*Cq];
__device__ float g_k[(long)Mq*Cq];
__device__ float g_v[(long)Mq*Cq];
__device__ float g_yy[(long)Mq*Cq];
__device__ float g_ctx[BHq*Dq*Dq];
__device__ float g_ksum[BHq*Dq];
__device__ float g_dinv[BHq*Tq];

// ---------------- PTX helpers (arch-generic, sm_80+) ----------------
__device__ __forceinline__ uint32_t smem_to_u32(const void* p) {
    uint32_t a;
    asm("{ .reg .u64 t; cvta.to.shared.u64 t, %1; cvt.u32.u64 %0, t; }" : "=r"(a) : "l"(p));
    return a;
}
#define CP_ASYNC16(dst, src) \
    asm volatile("cp.async.cg.shared.global [%0], [%1], 16;" :: "r"(dst), "l"(src))
#define CP_COMMIT() asm volatile("cp.async.commit_group;" ::: "memory")
#define CP_WAIT(n)  asm volatile("cp.async.wait_group %0;" :: "n"(n) : "memory")

__device__ __forceinline__ void ldm_x4(uint32_t& r0, uint32_t& r1, uint32_t& r2, uint32_t& r3,
                                       uint32_t a) {
    asm volatile("ldmatrix.sync.aligned.m8n8.x4.shared.b16 {%0,%1,%2,%3}, [%4];"
                 : "=r"(r0), "=r"(r1), "=r"(r2), "=r"(r3) : "r"(a));
}
__device__ __forceinline__ void mma16816(float* c, uint32_t a0, uint32_t a1, uint32_t a2,
                                         uint32_t a3, uint32_t b0, uint32_t b1) {
    asm volatile(
        "mma.sync.aligned.m16n8k16.row.col.f32.f16.f16.f32 "
        "{%0,%1,%2,%3}, {%4,%5,%6,%7}, {%8,%9}, {%0,%1,%2,%3};"
        : "+f"(c[0]), "+f"(c[1]), "+f"(c[2]), "+f"(c[3])
        : "r"(a0), "r"(a1), "r"(a2), "r"(a3), "r"(b0), "r"(b1));
}

// GEMM tiling
#define BKq   64
#define AST   72                 // smem row stride in halves (pad 64 -> 72, conflict-free)
#define ASTB  144                // bytes
#define TILEB (128*ASTB)         // 18432 bytes per tile buffer
#define NKCH  (KSP/BKq)          // 32 k-chunks
#define GEMM_SMEM (4*TILEB)      // 73728

// load one 128x64 fp16 tile (rows stride KSP in gmem) into smem via cp.async
__device__ __forceinline__ void load_tile(uint32_t sdst, const __half* g, int tid) {
#pragma unroll
    for (int i = 0; i < 4; i++) {
        int idx = tid + i * 256;
        int row = idx >> 3, seg = idx & 7;
        uint32_t d = sdst + row * ASTB + seg * 16;
        const char* s = (const char*)(g + (long)row * KSP) + seg * 16;
        CP_ASYNC16(d, s);
    }
}

// C[m0:+128, n0:+128] = A[m0:,:K'] @ Bw[n0:,:K']^T + bias
__device__ void gemm128(const __half* __restrict__ A,
                        const __half* __restrict__ Bw,
                        const float* __restrict__ bias, float* __restrict__ C,
                        int m0, int n0)
{
    extern __shared__ char smem[];
    const uint32_t sb = smem_to_u32(smem);
    const int tid = threadIdx.x, lane = tid & 31, wid = tid >> 5;
    const int wm = wid & 1;     // 0..1  -> 64-row slab
    const int wn = wid >> 1;    // 0..3  -> 32-col slab

    float acc[4][4][4];
#pragma unroll
    for (int i = 0; i < 4; i++)
#pragma unroll
        for (int j = 0; j < 4; j++)
#pragma unroll
            for (int r = 0; r < 4; r++) acc[i][j][r] = 0.f;

    const uint32_t aB[2] = { sb,             sb + TILEB     };
    const uint32_t bB[2] = { sb + 2*TILEB,   sb + 3*TILEB   };
    const __half* Ab = A + (long)m0 * KSP;
    const __half* Bb = Bw + (long)n0 * KSP;

    load_tile(aB[0], Ab, tid);
    load_tile(bB[0], Bb, tid);
    CP_COMMIT();

    // per-thread ldmatrix offsets
    const uint32_t aoff = (uint32_t)((wm*64 + (lane & 7) + ((lane >> 3) & 1) * 8) * ASTB
                                     + ((lane >> 4) * 8) * 2);
    const uint32_t boff = (uint32_t)((wn*32 + (lane & 7) + (lane >> 4) * 8) * ASTB
                                     + (((lane >> 3) & 1) * 8) * 2);

    for (int c = 0; c < NKCH; c++) {
        const int buf = c & 1;
        if (c + 1 < NKCH) {
            load_tile(aB[buf ^ 1], Ab + (c + 1) * BKq, tid);
            load_tile(bB[buf ^ 1], Bb + (c + 1) * BKq, tid);
            CP_COMMIT();
            CP_WAIT(1);
        } else {
            CP_WAIT(0);
        }
        __syncthreads();

#pragma unroll
        for (int kk = 0; kk < 4; kk++) {
            uint32_t a[4][4], b[2][4];
#pragma unroll
            for (int mi = 0; mi < 4; mi++)
                ldm_x4(a[mi][0], a[mi][1], a[mi][2], a[mi][3],
                       aB[buf] + aoff + mi * 16 * ASTB + kk * 32);
#pragma unroll
            for (int nf = 0; nf < 2; nf++)
                ldm_x4(b[nf][0], b[nf][1], b[nf][2], b[nf][3],
                       bB[buf] + boff + nf * 16 * ASTB + kk * 32);
#pragma unroll
            for (int mi = 0; mi < 4; mi++)
#pragma unroll
                for (int ni = 0; ni < 4; ni++)
                    mma16816(acc[mi][ni], a[mi][0], a[mi][1], a[mi][2], a[mi][3],
                             b[ni >> 1][(ni & 1) * 2], b[ni >> 1][(ni & 1) * 2 + 1]);
        }
        __syncthreads();
    }

    // epilogue
    const int r0 = wm * 64 + (lane >> 2);
    const int c0 = wn * 32 + (lane & 3) * 2;
#pragma unroll
    for (int mi = 0; mi < 4; mi++)
#pragma unroll
        for (int ni = 0; ni < 4; ni++) {
            int row = r0 + mi * 16;
            int col = c0 + ni * 8;
            float bx = bias[n0 + col], by = bias[n0 + col + 1];
            float2 o0 = make_float2(acc[mi][ni][0] + bx, acc[mi][ni][1] + by);
            float2 o1 = make_float2(acc[mi][ni][2] + bx, acc[mi][ni][3] + by);
            *(float2*)(C + (long)(m0 + row) * 1024 + n0 + col) = o0;
            *(float2*)(C + (long)(m0 + row + 8) * 1024 + n0 + col) = o1;
        }
}

// QKV fused: blockIdx.x in [0,24): sel = x>>3, ntile = x&7 (A-tile shared via L2)
__global__ __launch_bounds__(256, 2)
void qkv_gemm_kernel(const float* bq, const float* bk, const float* bv)
{
    const int sel = blockIdx.x >> 3;
    const int n0 = (blockIdx.x & 7) * 128;
    const int m0 = blockIdx.y * 128;
    const __half* W       = (sel == 0) ? g_wq : (sel == 1) ? g_wk : g_wv;
    const float* bias     = (sel == 0) ? bq  : (sel == 1) ? bk  : bv;
    float* C              = (sel == 0) ? g_q : (sel == 1) ? g_k : g_v;
    gemm128(g_xs, W, bias, C, m0, n0);
}

__global__ __launch_bounds__(256, 2)
void proj_gemm_kernel(const float* bp, float* out)
{
    gemm128(g_ys, g_wp, bp, out, blockIdx.y * 128, blockIdx.x * 128);
}

// ---------------- conversion kernels ----------------
// A' = [hi | lo] along K'  (pairs with B' = [hi | hi]);
// (a_hi + a_lo) * b_hi == a * fp16(b) to ~2^-22
__global__ void convert_a_kernel(const float* __restrict__ X, __half* __restrict__ O)
{
    long gid = (long)blockIdx.x * blockDim.x + threadIdx.x;
    long i = gid * 4;
    long m = i >> 10;
    int  k = (int)(i & 1023);
    float4 v = *(const float4*)(X + i);
    __half h[4], l[4];
    float vv[4] = {v.x, v.y, v.z, v.w};
#pragma unroll
    for (int j = 0; j < 4; j++) {
        h[j] = __float2half(vv[j]);
        l[j] = __float2half(vv[j] - __half2float(h[j]));
    }
    __half* base = O + m * KSP;
    *(uint2*)(base + k)        = *(uint2*)h;
    *(uint2*)(base + 1024 + k) = *(uint2*)l;
}

// W [K=1024][N=1024] -> O [n][k'=2048] transposed split: [hi | hi]
__global__ void convert_w_kernel(const float* __restrict__ W, __half* __restrict__ O)
{
    __shared__ float tile[32][33];
    const int n0 = blockIdx.x * 32, k0 = blockIdx.y * 32;
    const int tx = threadIdx.x & 31, ty = threadIdx.x >> 5;   // ty 0..7
#pragma unroll
    for (int r = 0; r < 32; r += 8)
        tile[ty + r][tx] = W[(long)(k0 + ty + r) * 1024 + n0 + tx];
    __syncthreads();
#pragma unroll
    for (int r = 0; r < 32; r += 8) {
        const int n = n0 + ty + r;
        float v = tile[tx][ty + r];
        __half hi = __float2half(v);
        __half* base = O + (long)n * KSP + k0 + tx;
        base[0]    = hi;
        base[1024] = hi;
    }
}

// ---------------- zero accumulators ----------------
__global__ void zero_kernel() {
    int i = blockIdx.x * blockDim.x + threadIdx.x;
    if (i < BHq*Dq*Dq) g_ctx[i] = 0.f;
    if (i < BHq*Dq)    g_ksum[i] = 0.f;
}

// ---------------- softmax over last dim (128), warp per row ----------------
__global__ void softmax_kernel(float* __restrict__ P, int nrows)
{
    int gw = (blockIdx.x * blockDim.x + threadIdx.x) >> 5;
    if (gw >= nrows) return;
    int lane = threadIdx.x & 31;
    float* p = P + (long)gw * 128 + lane * 4;
    float4 v = *(float4*)p;
    float mx = fmaxf(fmaxf(v.x, v.y), fmaxf(v.z, v.w));
#pragma unroll
    for (int o = 16; o; o >>= 1) mx = fmaxf(mx, __shfl_xor_sync(~0u, mx, o));
    v.x = expf(v.x - mx); v.y = expf(v.y - mx);
    v.z = expf(v.z - mx); v.w = expf(v.w - mx);
    float s = v.x + v.y + v.z + v.w;
#pragma unroll
    for (int o = 16; o; o >>= 1) s += __shfl_xor_sync(~0u, s, o);
    float inv = 1.f / s;
    v.x *= inv; v.y *= inv; v.z *= inv; v.w *= inv;
    *(float4*)p = v;
}

// ---------------- k_sum ----------------
__global__ void ksum_kernel()
{
    int bh = blockIdx.x;
    int b = bh >> 3, h = bh & 7;
    int t0 = blockIdx.y * 512;
    int d = threadIdx.x;
    const float* p = g_k + ((long)(b*Tq + t0)) * Cq + h*128 + d;
    float s = 0.f;
    for (int t = 0; t < 512; t++) s += p[(long)t * Cq];
    atomicAdd(&g_ksum[bh*128 + d], s);
}

// ---------------- D_inv ----------------
__global__ void dinv_kernel()
{
    int gw = (blockIdx.x * blockDim.x + threadIdx.x) >> 5;
    if (gw >= ROWSq) return;
    int lane = threadIdx.x & 31;
    int h = gw & 7;
    int bt = gw >> 3;
    int t = bt & (Tq - 1);
    int b = bt >> 13;
    float4 qv = *(const float4*)(g_q + (long)gw * 128 + lane * 4);
    float4 kv = *(const float4*)(g_ksum + (b*Hq + h) * 128 + lane * 4);
    float s = qv.x*kv.x + qv.y*kv.y + qv.z*kv.z + qv.w*kv.w;
#pragma unroll
    for (int o = 16; o; o >>= 1) s += __shfl_xor_sync(~0u, s, o);
    if (!lane) g_dinv[(long)(b*Hq + h) * Tq + t] = 1.f / s;
}

// ---------------- context = K^T V (split-T, atomics) ----------------
__global__ __launch_bounds__(256, 2)
void ctx_kernel()
{
    __shared__ float As[2][16][128];
    __shared__ float Bs[2][16][128];
    const int bh = blockIdx.x;
    const int b = bh >> 3, h = bh & 7;
    const int t0 = blockIdx.y * 512;
    const int tid = threadIdx.x;
    const int tx = tid & 15, ty = tid >> 4;
    const int lRow = tid >> 5;
    const int lCol = (tid & 31) << 2;

    const float* kb = g_k + ((long)(b*Tq + t0 + lRow)) * Cq + h*128 + lCol;
    const float* vb = g_v + ((long)(b*Tq + t0 + lRow)) * Cq + h*128 + lCol;

    float acc[8][8];
#pragma unroll
    for (int i = 0; i < 8; i++)
#pragma unroll
        for (int j = 0; j < 8; j++) acc[i][j] = 0.f;

    float4 pa0, pa1, pb0, pb1;
    pa0 = *(const float4*)(kb);
    pa1 = *(const float4*)(kb + 8L*Cq);
    pb0 = *(const float4*)(vb);
    pb1 = *(const float4*)(vb + 8L*Cq);
    *(float4*)&As[0][lRow][lCol]   = pa0;
    *(float4*)&As[0][lRow+8][lCol] = pa1;
    *(float4*)&Bs[0][lRow][lCol]   = pb0;
    *(float4*)&Bs[0][lRow+8][lCol] = pb1;
    __syncthreads();

    const int nk = 32;
    for (int kt = 0; kt < nk; kt++) {
        const int buf = kt & 1;
        if (kt + 1 < nk) {
            long off = (long)((kt + 1) * 16) * Cq;
            pa0 = *(const float4*)(kb + off);
            pa1 = *(const float4*)(kb + off + 8L*Cq);
            pb0 = *(const float4*)(vb + off);
            pb1 = *(const float4*)(vb + off + 8L*Cq);
        }
#pragma unroll
        for (int kk = 0; kk < 16; kk++) {
            float4 a0 = *(const float4*)&As[buf][kk][ty*8];
            float4 a1 = *(const float4*)&As[buf][kk][ty*8+4];
            float4 b0 = *(const float4*)&Bs[buf][kk][tx*8];
            float4 b1 = *(const float4*)&Bs[buf][kk][tx*8+4];
            float a[8] = {a0.x,a0.y,a0.z,a0.w,a1.x,a1.y,a1.z,a1.w};
            float bb[8] = {b0.x,b0.y,b0.z,b0.w,b1.x,b1.y,b1.z,b1.w};
#pragma unroll
            for (int i = 0; i < 8; i++)
#pragma unroll
                for (int j = 0; j < 8; j++) acc[i][j] += a[i] * bb[j];
        }
        if (kt + 1 < nk) {
            const int nb = buf ^ 1;
            *(float4*)&As[nb][lRow][lCol]   = pa0;
            *(float4*)&As[nb][lRow+8][lCol] = pa1;
            *(float4*)&Bs[nb][lRow][lCol]   = pb0;
            *(float4*)&Bs[nb][lRow+8][lCol] = pb1;
        }
        __syncthreads();
    }

    float* cbase = g_ctx + (long)bh * Dq * Dq;
#pragma unroll
    for (int i = 0; i < 8; i++)
#pragma unroll
        for (int j = 0; j < 8; j++)
            atomicAdd(&cbase[(ty*8 + i) * 128 + tx*8 + j], acc[i][j]);
}

// ---------------- y = (q @ ctx) * Dinv + q ----------------
__global__ __launch_bounds__(256, 2)
void y_kernel()
{
    __shared__ float As[2][16][128];
    __shared__ float Bs[2][16][128];
    __shared__ float dinv_s[128];
    const int bh = blockIdx.x;
    const int b = bh >> 3, h = bh & 7;
    const int t0 = blockIdx.y * 128;
    const int tid = threadIdx.x;
    const int tx = tid & 15, ty = tid >> 4;

    if (tid < 128) dinv_s[tid] = g_dinv[(long)bh * Tq + t0 + tid];

    const int aRow = tid >> 2;
    const int aCol = (tid & 3) << 2;
    const int bRow = tid >> 5;
    const int bCol = (tid & 31) << 2;

    const float* qb = g_q + ((long)(b*Tq + t0 + aRow)) * Cq + h*128 + aCol;
    const float* cb = g_ctx + (long)bh * Dq * Dq + bRow * 128 + bCol;

    float acc[8][8];
#pragma unroll
    for (int i = 0; i < 8; i++)
#pragma unroll
        for (int j = 0; j < 8; j++) acc[i][j] = 0.f;

    float4 pa0, pa1, pb0, pb1;
    pa0 = *(const float4*)(qb);
    pa1 = *(const float4*)(qb + 64L*Cq);
    pb0 = *(const float4*)(cb);
    pb1 = *(const float4*)(cb + 8L*128);
    As[0][aCol+0][aRow]    = pa0.x; As[0][aCol+1][aRow]    = pa0.y;
    As[0][aCol+2][aRow]    = pa0.z; As[0][aCol+3][aRow]    = pa0.w;
    As[0][aCol+0][aRow+64] = pa1.x; As[0][aCol+1][aRow+64] = pa1.y;
    As[0][aCol+2][aRow+64] = pa1.z; As[0][aCol+3][aRow+64] = pa1.w;
    *(float4*)&Bs[0][bRow][bCol]   = pb0;
    *(float4*)&Bs[0][bRow+8][bCol] = pb1;
    __syncthreads();

    const int nk = 8;
    for (int kt = 0; kt < nk; kt++) {
        const int buf = kt & 1;
        if (kt + 1 < nk) {
            const int k0 = (kt + 1) << 4;
            pa0 = *(const float4*)(qb + k0);
            pa1 = *(const float4*)(qb + 64L*Cq + k0);
            pb0 = *(const float4*)(cb + k0 * 128);
            pb1 = *(const float4*)(cb + (k0 + 8) * 128);
        }
#pragma unroll
        for (int kk = 0; kk < 16; kk++) {
            float4 a0 = *(const float4*)&As[buf][kk][ty*8];
            float4 a1 = *(const float4*)&As[buf][kk][ty*8+4];
            float4 b0 = *(const float4*)&Bs[buf][kk][tx*8];
            float4 b1 = *(const float4*)&Bs[buf][kk][tx*8+4];
            float a[8] = {a0.x,a0.y,a0.z,a0.w,a1.x,a1.y,a1.z,a1.w};
            float bb[8] = {b0.x,b0.y,b0.z,b0.w,b1.x,b1.y,b1.z,b1.w};
#pragma unroll
            for (int i = 0; i < 8; i++)
#pragma unroll
                for (int j = 0; j < 8; j++) acc[i][j] += a[i] * bb[j];
        }
        if (kt + 1 < nk) {
            const int nb = buf ^ 1;
            As[nb][aCol+0][aRow]    = pa0.x; As[nb][aCol+1][aRow]    = pa0.y;
            As[nb][aCol+2][aRow]    = pa0.z; As[nb][aCol+3][aRow]    = pa0.w;
            As[nb][aCol+0][aRow+64] = pa1.x; As[nb][aCol+1][aRow+64] = pa1.y;
            As[nb][aCol+2][aRow+64] = pa1.z; As[nb][aCol+3][aRow+64] = pa1.w;
            *(float4*)&Bs[nb][bRow][bCol]   = pb0;
            *(float4*)&Bs[nb][bRow+8][bCol] = pb1;
        }
        __syncthreads();
    }

#pragma unroll
    for (int i = 0; i < 8; i++) {
        int m = ty*8 + i;
        float dv = dinv_s[m];
        long gi = ((long)(b*Tq + t0 + m)) * Cq + h*128 + tx*8;
        float4 q0 = *(const float4*)(g_q + gi);
        float4 q1 = *(const float4*)(g_q + gi + 4);
        float4 o0 = make_float4(acc[i][0]*dv + q0.x, acc[i][1]*dv + q0.y,
                                acc[i][2]*dv + q0.z, acc[i][3]*dv + q0.w);
        float4 o1 = make_float4(acc[i][4]*dv + q1.x, acc[i][5]*dv + q1.y,
                                acc[i][6]*dv + q1.z, acc[i][7]*dv + q1.w);
        *(float4*)(g_yy + gi)     = o0;
        *(float4*)(g_yy + gi + 4) = o1;
    }
}

// ---------------------------------------------------------------------------
extern "C" void kernel_launch(void* const* d_in, const int* in_sizes, int n_in,
                              void* d_out, int out_size)
{
    const float* x  = (const float*)d_in[0];
    const float* Wq = (const float*)d_in[1];
    const float* bq = (const float*)d_in[2];
    const float* Wk = (const float*)d_in[3];
    const float* bk = (const float*)d_in[4];
    const float* Wv = (const float*)d_in[5];
    const float* bv = (const float*)d_in[6];
    const float* Wp = (const float*)d_in[7];
    const float* bp = (const float*)d_in[8];
    float* out = (float*)d_out;

    float *pq, *pk, *pyy;
    __half *pxs, *pys, *pwq, *pwk, *pwv, *pwp;
    cudaGetSymbolAddress((void**)&pq,  g_q);
    cudaGetSymbolAddress((void**)&pk,  g_k);
    cudaGetSymbolAddress((void**)&pyy, g_yy);
    cudaGetSymbolAddress((void**)&pxs, g_xs);
    cudaGetSymbolAddress((void**)&pys, g_ys);
    cudaGetSymbolAddress((void**)&pwq, g_wq);
    cudaGetSymbolAddress((void**)&pwk, g_wk);
    cudaGetSymbolAddress((void**)&pwv, g_wv);
    cudaGetSymbolAddress((void**)&pwp, g_wp);

    cudaFuncSetAttribute(qkv_gemm_kernel,  cudaFuncAttributeMaxDynamicSharedMemorySize, GEMM_SMEM);
    cudaFuncSetAttribute(proj_gemm_kernel, cudaFuncAttributeMaxDynamicSharedMemorySize, GEMM_SMEM);

    zero_kernel<<<2048, 256>>>();

    convert_a_kernel<<<Mq*Cq/4/256, 256>>>(x, pxs);
    convert_w_kernel<<<dim3(32,32), 256>>>(Wq, pwq);
    convert_w_kernel<<<dim3(32,32), 256>>>(Wk, pwk);
    convert_w_kernel<<<dim3(32,32), 256>>>(Wv, pwv);
    convert_w_kernel<<<dim3(32,32), 256>>>(Wp, pwp);

    qkv_gemm_kernel<<<dim3(24, Mq/128), 256, GEMM_SMEM>>>(bq, bk, bv);

    softmax_kernel<<<ROWSq/8, 256>>>(pq, ROWSq);
    softmax_kernel<<<ROWSq/8, 256>>>(pk, ROWSq);

    ksum_kernel<<<dim3(BHq, 16), 128>>>();
    dinv_kernel<<<ROWSq/8, 256>>>();
    ctx_kernel<<<dim3(BHq, 16), 256>>>();
    y_kernel<<<dim3(BHq, Tq/128), 256>>>();

    convert_a_kernel<<<Mq*Cq/4/256, 256>>>(pyy, pys);
    proj_gemm_kernel<<<dim3(8, Mq/128), 256, GEMM_SMEM>>>(bp, out);
}

// round 5
// speedup vs baseline: 3.2531x; 1.0634x over previous
#include <cuda_runtime.h>
#include <cuda_fp16.h>
#include <cstdint>

// Problem constants
#define Bq    4
#define Tq    8192
#define Cq    1024
#define Hq    8
#define Dq    128
#define Mq    (Bq*Tq)          // 32768
#define BHq   (Bq*Hq)          // 32
#define ROWSq (Mq*Hq)          // 262144 rows of 128
#define KSP   2048             // split-K' = 2*1024 (fp16 2-term)

// ---------------- device scratch (static, no allocation) ----------------
__device__ __half g_xs[(long)Mq*KSP];   // x split   [m][k']  128MB
__device__ __half g_ys[(long)Mq*KSP];   // y split   [m][k']  128MB
__device__ __half g_wq[1024*KSP];       // W^T split [n][k']  4MB
__device__ __half g_wk[1024*KSP];
__device__ __half g_wv[1024*KSP];
__device__ __half g_wp[1024*KSP];
__device__ float g_q[(long)Mq*Cq];
__device__ float g_k[(long)Mq*Cq];
__device__ float g_v[(long)Mq*Cq];
__device__ float g_ctx[BHq*Dq*Dq];
__device__ float g_ksum[BHq*Dq];
__device__ float g_dinv[BHq*Tq];

// ---------------- PTX helpers (arch-generic, sm_80+) ----------------
__device__ __forceinline__ uint32_t smem_to_u32(const void* p) {
    uint32_t a;
    asm("{ .reg .u64 t; cvta.to.shared.u64 t, %1; cvt.u32.u64 %0, t; }" : "=r"(a) : "l"(p));
    return a;
}
#define CP_ASYNC16(dst, src) \
    asm volatile("cp.async.cg.shared.global [%0], [%1], 16;" :: "r"(dst), "l"(src))
#define CP_COMMIT() asm volatile("cp.async.commit_group;" ::: "memory")
#define CP_WAIT(n)  asm volatile("cp.async.wait_group %0;" :: "n"(n) : "memory")

__device__ __forceinline__ void ldm_x4(uint32_t& r0, uint32_t& r1, uint32_t& r2, uint32_t& r3,
                                       uint32_t a) {
    asm volatile("ldmatrix.sync.aligned.m8n8.x4.shared.b16 {%0,%1,%2,%3}, [%4];"
                 : "=r"(r0), "=r"(r1), "=r"(r2), "=r"(r3) : "r"(a));
}
__device__ __forceinline__ void mma16816(float* c, uint32_t a0, uint32_t a1, uint32_t a2,
                                         uint32_t a3, uint32_t b0, uint32_t b1) {
    asm volatile(
        "mma.sync.aligned.m16n8k16.row.col.f32.f16.f16.f32 "
        "{%0,%1,%2,%3}, {%4,%5,%6,%7}, {%8,%9}, {%0,%1,%2,%3};"
        : "+f"(c[0]), "+f"(c[1]), "+f"(c[2]), "+f"(c[3])
        : "r"(a0), "r"(a1), "r"(a2), "r"(a3), "r"(b0), "r"(b1));
}

// GEMM tiling
#define BKq   64
#define AST   72                 // smem row stride in halves (pad 64 -> 72, conflict-free)
#define ASTB  144                // bytes
#define TILEB (128*ASTB)         // 18432 bytes per tile buffer
#define NKCH  (KSP/BKq)          // 32 k-chunks
#define GEMM_SMEM (4*TILEB)      // 73728

// load one 128x64 fp16 tile (rows stride KSP in gmem) into smem via cp.async
__device__ __forceinline__ void load_tile(uint32_t sdst, const __half* g, int tid) {
#pragma unroll
    for (int i = 0; i < 4; i++) {
        int idx = tid + i * 256;
        int row = idx >> 3, seg = idx & 7;
        uint32_t d = sdst + row * ASTB + seg * 16;
        const char* s = (const char*)(g + (long)row * KSP) + seg * 16;
        CP_ASYNC16(d, s);
    }
}

// modes: 0 = plain (bias+store), 1 = softmax (q), 2 = softmax + fused ksum (k)
__device__ void gemm128(const __half* __restrict__ A,
                        const __half* __restrict__ Bw,
                        const float* __restrict__ bias, float* __restrict__ C,
                        int m0, int n0, int mode)
{
    extern __shared__ char smem[];
    const uint32_t sb = smem_to_u32(smem);
    const int tid = threadIdx.x, lane = tid & 31, wid = tid >> 5;
    const int wm = wid & 1;     // 0..1  -> 64-row slab
    const int wn = wid >> 1;    // 0..3  -> 32-col slab

    float acc[4][4][4];
#pragma unroll
    for (int i = 0; i < 4; i++)
#pragma unroll
        for (int j = 0; j < 4; j++)
#pragma unroll
            for (int r = 0; r < 4; r++) acc[i][j][r] = 0.f;

    const uint32_t aB[2] = { sb,             sb + TILEB     };
    const uint32_t bB[2] = { sb + 2*TILEB,   sb + 3*TILEB   };
    const __half* Ab = A + (long)m0 * KSP;
    const __half* Bb = Bw + (long)n0 * KSP;

    load_tile(aB[0], Ab, tid);
    load_tile(bB[0], Bb, tid);
    CP_COMMIT();

    const uint32_t aoff = (uint32_t)((wm*64 + (lane & 7) + ((lane >> 3) & 1) * 8) * ASTB
                                     + ((lane >> 4) * 8) * 2);
    const uint32_t boff = (uint32_t)((wn*32 + (lane & 7) + (lane >> 4) * 8) * ASTB
                                     + (((lane >> 3) & 1) * 8) * 2);

    for (int c = 0; c < NKCH; c++) {
        const int buf = c & 1;
        if (c + 1 < NKCH) {
            load_tile(aB[buf ^ 1], Ab + (c + 1) * BKq, tid);
            load_tile(bB[buf ^ 1], Bb + (c + 1) * BKq, tid);
            CP_COMMIT();
            CP_WAIT(1);
        } else {
            CP_WAIT(0);
        }
        __syncthreads();

#pragma unroll
        for (int kk = 0; kk < 4; kk++) {
            uint32_t a[4][4], b[2][4];
#pragma unroll
            for (int mi = 0; mi < 4; mi++)
                ldm_x4(a[mi][0], a[mi][1], a[mi][2], a[mi][3],
                       aB[buf] + aoff + mi * 16 * ASTB + kk * 32);
#pragma unroll
            for (int nf = 0; nf < 2; nf++)
                ldm_x4(b[nf][0], b[nf][1], b[nf][2], b[nf][3],
                       bB[buf] + boff + nf * 16 * ASTB + kk * 32);
#pragma unroll
            for (int mi = 0; mi < 4; mi++)
#pragma unroll
                for (int ni = 0; ni < 4; ni++)
                    mma16816(acc[mi][ni], a[mi][0], a[mi][1], a[mi][2], a[mi][3],
                             b[ni >> 1][(ni & 1) * 2], b[ni >> 1][(ni & 1) * 2 + 1]);
        }
        __syncthreads();
    }

    // ----- epilogue -----
    const int rb = wm * 64 + (lane >> 2);      // base row (thread rows: rb+mi*16, +8)
    const int cb = wn * 32 + (lane & 3) * 2;   // base col (thread cols: cb+ni*8, +1)

    // bias first (softmax is shift-invariant but reference adds bias pre-softmax;
    // for plain mode this is just the normal epilogue bias)
#pragma unroll
    for (int ni = 0; ni < 4; ni++) {
        float bx = bias[n0 + cb + ni*8];
        float by = bias[n0 + cb + ni*8 + 1];
#pragma unroll
        for (int mi = 0; mi < 4; mi++) {
            acc[mi][ni][0] += bx; acc[mi][ni][1] += by;
            acc[mi][ni][2] += bx; acc[mi][ni][3] += by;
        }
    }

    if (mode >= 1) {
        float* red = (float*)smem;      // [4][128], reuses dead tile smem
        float rm[4][2];
        // per-row max: local over 8 cols, then across the 4 col-lanes
#pragma unroll
        for (int mi = 0; mi < 4; mi++) {
            float m0v = -1e30f, m1v = -1e30f;
#pragma unroll
            for (int ni = 0; ni < 4; ni++) {
                m0v = fmaxf(m0v, fmaxf(acc[mi][ni][0], acc[mi][ni][1]));
                m1v = fmaxf(m1v, fmaxf(acc[mi][ni][2], acc[mi][ni][3]));
            }
            m0v = fmaxf(m0v, __shfl_xor_sync(~0u, m0v, 1));
            m0v = fmaxf(m0v, __shfl_xor_sync(~0u, m0v, 2));
            m1v = fmaxf(m1v, __shfl_xor_sync(~0u, m1v, 1));
            m1v = fmaxf(m1v, __shfl_xor_sync(~0u, m1v, 2));
            rm[mi][0] = m0v; rm[mi][1] = m1v;
        }
        if ((lane & 3) == 0)
#pragma unroll
            for (int mi = 0; mi < 4; mi++) {
                red[wn*128 + rb + mi*16]     = rm[mi][0];
                red[wn*128 + rb + mi*16 + 8] = rm[mi][1];
            }
        __syncthreads();
#pragma unroll
        for (int mi = 0; mi < 4; mi++) {
            int r0i = rb + mi*16;
            rm[mi][0] = fmaxf(fmaxf(red[r0i], red[128 + r0i]),
                              fmaxf(red[256 + r0i], red[384 + r0i]));
            rm[mi][1] = fmaxf(fmaxf(red[r0i+8], red[128 + r0i+8]),
                              fmaxf(red[256 + r0i+8], red[384 + r0i+8]));
        }
        __syncthreads();   // before red reuse
        // exp + row sum
        float rs[4][2];
#pragma unroll
        for (int mi = 0; mi < 4; mi++) {
            float s0 = 0.f, s1 = 0.f;
#pragma unroll
            for (int ni = 0; ni < 4; ni++) {
                acc[mi][ni][0] = __expf(acc[mi][ni][0] - rm[mi][0]); s0 += acc[mi][ni][0];
                acc[mi][ni][1] = __expf(acc[mi][ni][1] - rm[mi][0]); s0 += acc[mi][ni][1];
                acc[mi][ni][2] = __expf(acc[mi][ni][2] - rm[mi][1]); s1 += acc[mi][ni][2];
                acc[mi][ni][3] = __expf(acc[mi][ni][3] - rm[mi][1]); s1 += acc[mi][ni][3];
            }
            s0 += __shfl_xor_sync(~0u, s0, 1); s0 += __shfl_xor_sync(~0u, s0, 2);
            s1 += __shfl_xor_sync(~0u, s1, 1); s1 += __shfl_xor_sync(~0u, s1, 2);
            rs[mi][0] = s0; rs[mi][1] = s1;
        }
        if ((lane & 3) == 0)
#pragma unroll
            for (int mi = 0; mi < 4; mi++) {
                red[wn*128 + rb + mi*16]     = rs[mi][0];
                red[wn*128 + rb + mi*16 + 8] = rs[mi][1];
            }
        __syncthreads();
#pragma unroll
        for (int mi = 0; mi < 4; mi++) {
            int r0i = rb + mi*16;
            float inv0 = 1.f / (red[r0i] + red[128 + r0i] + red[256 + r0i] + red[384 + r0i]);
            float inv1 = 1.f / (red[r0i+8] + red[128 + r0i+8] + red[256 + r0i+8] + red[384 + r0i+8]);
#pragma unroll
            for (int ni = 0; ni < 4; ni++) {
                acc[mi][ni][0] *= inv0; acc[mi][ni][1] *= inv0;
                acc[mi][ni][2] *= inv1; acc[mi][ni][3] *= inv1;
            }
        }
    }

    // store
#pragma unroll
    for (int mi = 0; mi < 4; mi++)
#pragma unroll
        for (int ni = 0; ni < 4; ni++) {
            int row = rb + mi * 16;
            int col = cb + ni * 8;
            float2 o0 = make_float2(acc[mi][ni][0], acc[mi][ni][1]);
            float2 o1 = make_float2(acc[mi][ni][2], acc[mi][ni][3]);
            *(float2*)(C + (long)(m0 + row) * 1024 + n0 + col) = o0;
            *(float2*)(C + (long)(m0 + row + 8) * 1024 + n0 + col) = o1;
        }

    // fused ksum (k only): column sums over this block's 128 rows
    if (mode == 2) {
        float cs[8];
#pragma unroll
        for (int ni = 0; ni < 4; ni++)
#pragma unroll
            for (int p = 0; p < 2; p++) {
                float s = 0.f;
#pragma unroll
                for (int mi = 0; mi < 4; mi++)
                    s += acc[mi][ni][p] + acc[mi][ni][p + 2];
                cs[ni*2 + p] = s;
            }
#pragma unroll
        for (int j = 0; j < 8; j++) {
            cs[j] += __shfl_xor_sync(~0u, cs[j], 4);
            cs[j] += __shfl_xor_sync(~0u, cs[j], 8);
            cs[j] += __shfl_xor_sync(~0u, cs[j], 16);
        }
        if (lane < 4) {
            const int bh = (m0 >> 13) * 8 + (n0 >> 7);
#pragma unroll
            for (int j = 0; j < 8; j++)
                atomicAdd(&g_ksum[bh*128 + cb + (j >> 1)*8 + (j & 1)], cs[j]);
        }
    }
}

// QKV fused: blockIdx.x in [0,24): sel = x>>3, ntile = x&7 (A-tile shared via L2)
__global__ __launch_bounds__(256, 2)
void qkv_gemm_kernel(const float* bq, const float* bk, const float* bv)
{
    const int sel = blockIdx.x >> 3;
    const int n0 = (blockIdx.x & 7) * 128;
    const int m0 = blockIdx.y * 128;
    const __half* W       = (sel == 0) ? g_wq : (sel == 1) ? g_wk : g_wv;
    const float* bias     = (sel == 0) ? bq  : (sel == 1) ? bk  : bv;
    float* C              = (sel == 0) ? g_q : (sel == 1) ? g_k : g_v;
    const int mode        = (sel == 0) ? 1   : (sel == 1) ? 2   : 0;
    gemm128(g_xs, W, bias, C, m0, n0, mode);
}

__global__ __launch_bounds__(256, 2)
void proj_gemm_kernel(const float* bp, float* out)
{
    gemm128(g_ys, g_wp, bp, out, blockIdx.y * 128, blockIdx.x * 128, 0);
}

// ---------------- conversion kernels ----------------
// A' = [hi | lo] along K'  (pairs with B' = [hi | hi]);
__global__ void convert_a_kernel(const float* __restrict__ X, __half* __restrict__ O)
{
    long gid = (long)blockIdx.x * blockDim.x + threadIdx.x;
    long i = gid * 4;
    long m = i >> 10;
    int  k = (int)(i & 1023);
    float4 v = *(const float4*)(X + i);
    __half h[4], l[4];
    float vv[4] = {v.x, v.y, v.z, v.w};
#pragma unroll
    for (int j = 0; j < 4; j++) {
        h[j] = __float2half(vv[j]);
        l[j] = __float2half(vv[j] - __half2float(h[j]));
    }
    __half* base = O + m * KSP;
    *(uint2*)(base + k)        = *(uint2*)h;
    *(uint2*)(base + 1024 + k) = *(uint2*)l;
}

// W [K=1024][N=1024] -> O [n][k'=2048] transposed split: [hi | hi]
__global__ void convert_w_kernel(const float* __restrict__ W, __half* __restrict__ O)
{
    __shared__ float tile[32][33];
    const int n0 = blockIdx.x * 32, k0 = blockIdx.y * 32;
    const int tx = threadIdx.x & 31, ty = threadIdx.x >> 5;
#pragma unroll
    for (int r = 0; r < 32; r += 8)
        tile[ty + r][tx] = W[(long)(k0 + ty + r) * 1024 + n0 + tx];
    __syncthreads();
#pragma unroll
    for (int r = 0; r < 32; r += 8) {
        const int n = n0 + ty + r;
        float v = tile[tx][ty + r];
        __half hi = __float2half(v);
        __half* base = O + (long)n * KSP + k0 + tx;
        base[0]    = hi;
        base[1024] = hi;
    }
}

// ---------------- zero accumulators ----------------
__global__ void zero_kernel() {
    int i = blockIdx.x * blockDim.x + threadIdx.x;
    if (i < BHq*Dq*Dq) g_ctx[i] = 0.f;
    if (i < BHq*Dq)    g_ksum[i] = 0.f;
}

// ---------------- D_inv ----------------
__global__ void dinv_kernel()
{
    int gw = (blockIdx.x * blockDim.x + threadIdx.x) >> 5;
    if (gw >= ROWSq) return;
    int lane = threadIdx.x & 31;
    int h = gw & 7;
    int bt = gw >> 3;
    int t = bt & (Tq - 1);
    int b = bt >> 13;
    float4 qv = *(const float4*)(g_q + (long)gw * 128 + lane * 4);
    float4 kv = *(const float4*)(g_ksum + (b*Hq + h) * 128 + lane * 4);
    float s = qv.x*kv.x + qv.y*kv.y + qv.z*kv.z + qv.w*kv.w;
#pragma unroll
    for (int o = 16; o; o >>= 1) s += __shfl_xor_sync(~0u, s, o);
    if (!lane) g_dinv[(long)(b*Hq + h) * Tq + t] = 1.f / s;
}

// ---------------- context = K^T V (split-T, atomics) ----------------
__global__ __launch_bounds__(256, 2)
void ctx_kernel()
{
    __shared__ float As[2][16][128];
    __shared__ float Bs[2][16][128];
    const int bh = blockIdx.x;
    const int b = bh >> 3, h = bh & 7;
    const int t0 = blockIdx.y * 512;
    const int tid = threadIdx.x;
    const int tx = tid & 15, ty = tid >> 4;
    const int lRow = tid >> 5;
    const int lCol = (tid & 31) << 2;

    const float* kb = g_k + ((long)(b*Tq + t0 + lRow)) * Cq + h*128 + lCol;
    const float* vb = g_v + ((long)(b*Tq + t0 + lRow)) * Cq + h*128 + lCol;

    float acc[8][8];
#pragma unroll
    for (int i = 0; i < 8; i++)
#pragma unroll
        for (int j = 0; j < 8; j++) acc[i][j] = 0.f;

    float4 pa0, pa1, pb0, pb1;
    pa0 = *(const float4*)(kb);
    pa1 = *(const float4*)(kb + 8L*Cq);
    pb0 = *(const float4*)(vb);
    pb1 = *(const float4*)(vb + 8L*Cq);
    *(float4*)&As[0][lRow][lCol]   = pa0;
    *(float4*)&As[0][lRow+8][lCol] = pa1;
    *(float4*)&Bs[0][lRow][lCol]   = pb0;
    *(float4*)&Bs[0][lRow+8][lCol] = pb1;
    __syncthreads();

    const int nk = 32;
    for (int kt = 0; kt < nk; kt++) {
        const int buf = kt & 1;
        if (kt + 1 < nk) {
            long off = (long)((kt + 1) * 16) * Cq;
            pa0 = *(const float4*)(kb + off);
            pa1 = *(const float4*)(kb + off + 8L*Cq);
            pb0 = *(const float4*)(vb + off);
            pb1 = *(const float4*)(vb + off + 8L*Cq);
        }
#pragma unroll
        for (int kk = 0; kk < 16; kk++) {
            float4 a0 = *(const float4*)&As[buf][kk][ty*8];
            float4 a1 = *(const float4*)&As[buf][kk][ty*8+4];
            float4 b0 = *(const float4*)&Bs[buf][kk][tx*8];
            float4 b1 = *(const float4*)&Bs[buf][kk][tx*8+4];
            float a[8] = {a0.x,a0.y,a0.z,a0.w,a1.x,a1.y,a1.z,a1.w};
            float bb[8] = {b0.x,b0.y,b0.z,b0.w,b1.x,b1.y,b1.z,b1.w};
#pragma unroll
            for (int i = 0; i < 8; i++)
#pragma unroll
                for (int j = 0; j < 8; j++) acc[i][j] += a[i] * bb[j];
        }
        if (kt + 1 < nk) {
            const int nb = buf ^ 1;
            *(float4*)&As[nb][lRow][lCol]   = pa0;
            *(float4*)&As[nb][lRow+8][lCol] = pa1;
            *(float4*)&Bs[nb][lRow][lCol]   = pb0;
            *(float4*)&Bs[nb][lRow+8][lCol] = pb1;
        }
        __syncthreads();
    }

    float* cbase = g_ctx + (long)bh * Dq * Dq;
#pragma unroll
    for (int i = 0; i < 8; i++)
#pragma unroll
        for (int j = 0; j < 8; j++)
            atomicAdd(&cbase[(ty*8 + i) * 128 + tx*8 + j], acc[i][j]);
}

// ---------------- y = (q @ ctx) * Dinv + q  -> fp16 split into g_ys ----------------
__global__ __launch_bounds__(256, 2)
void y_kernel()
{
    __shared__ float As[2][16][128];
    __shared__ float Bs[2][16][128];
    __shared__ float dinv_s[128];
    const int bh = blockIdx.x;
    const int b = bh >> 3, h = bh & 7;
    const int t0 = blockIdx.y * 128;
    const int tid = threadIdx.x;
    const int tx = tid & 15, ty = tid >> 4;

    if (tid < 128) dinv_s[tid] = g_dinv[(long)bh * Tq + t0 + tid];

    const int aRow = tid >> 2;
    const int aCol = (tid & 3) << 2;
    const int bRow = tid >> 5;
    const int bCol = (tid & 31) << 2;

    const float* qb = g_q + ((long)(b*Tq + t0 + aRow)) * Cq + h*128 + aCol;
    const float* cb = g_ctx + (long)bh * Dq * Dq + bRow * 128 + bCol;

    float acc[8][8];
#pragma unroll
    for (int i = 0; i < 8; i++)
#pragma unroll
        for (int j = 0; j < 8; j++) acc[i][j] = 0.f;

    float4 pa0, pa1, pb0, pb1;
    pa0 = *(const float4*)(qb);
    pa1 = *(const float4*)(qb + 64L*Cq);
    pb0 = *(const float4*)(cb);
    pb1 = *(const float4*)(cb + 8L*128);
    As[0][aCol+0][aRow]    = pa0.x; As[0][aCol+1][aRow]    = pa0.y;
    As[0][aCol+2][aRow]    = pa0.z; As[0][aCol+3][aRow]    = pa0.w;
    As[0][aCol+0][aRow+64] = pa1.x; As[0][aCol+1][aRow+64] = pa1.y;
    As[0][aCol+2][aRow+64] = pa1.z; As[0][aCol+3][aRow+64] = pa1.w;
    *(float4*)&Bs[0][bRow][bCol]   = pb0;
    *(float4*)&Bs[0][bRow+8][bCol] = pb1;
    __syncthreads();

    const int nk = 8;
    for (int kt = 0; kt < nk; kt++) {
        const int buf = kt & 1;
        if (kt + 1 < nk) {
            const int k0 = (kt + 1) << 4;
            pa0 = *(const float4*)(qb + k0);
            pa1 = *(const float4*)(qb + 64L*Cq + k0);
            pb0 = *(const float4*)(cb + k0 * 128);
            pb1 = *(const float4*)(cb + (k0 + 8) * 128);
        }
#pragma unroll
        for (int kk = 0; kk < 16; kk++) {
            float4 a0 = *(const float4*)&As[buf][kk][ty*8];
            float4 a1 = *(const float4*)&As[buf][kk][ty*8+4];
            float4 b0 = *(const float4*)&Bs[buf][kk][tx*8];
            float4 b1 = *(const float4*)&Bs[buf][kk][tx*8+4];
            float a[8] = {a0.x,a0.y,a0.z,a0.w,a1.x,a1.y,a1.z,a1.w};
            float bb[8] = {b0.x,b0.y,b0.z,b0.w,b1.x,b1.y,b1.z,b1.w};
#pragma unroll
            for (int i = 0; i < 8; i++)
#pragma unroll
                for (int j = 0; j < 8; j++) acc[i][j] += a[i] * bb[j];
        }
        if (kt + 1 < nk) {
            const int nb = buf ^ 1;
            As[nb][aCol+0][aRow]    = pa0.x; As[nb][aCol+1][aRow]    = pa0.y;
            As[nb][aCol+2][aRow]    = pa0.z; As[nb][aCol+3][aRow]    = pa0.w;
            As[nb][aCol+0][aRow+64] = pa1.x; As[nb][aCol+1][aRow+64] = pa1.y;
            As[nb][aCol+2][aRow+64] = pa1.z; As[nb][aCol+3][aRow+64] = pa1.w;
            *(float4*)&Bs[nb][bRow][bCol]   = pb0;
            *(float4*)&Bs[nb][bRow+8][bCol] = pb1;
        }
        __syncthreads();
    }

#pragma unroll
    for (int i = 0; i < 8; i++) {
        int m = ty*8 + i;
        float dv = dinv_s[m];
        long mg = (long)(b*Tq + t0 + m);
        long gi = mg * Cq + h*128 + tx*8;
        float4 q0 = *(const float4*)(g_q + gi);
        float4 q1 = *(const float4*)(g_q + gi + 4);
        float o[8];
        o[0]=acc[i][0]*dv+q0.x; o[1]=acc[i][1]*dv+q0.y;
        o[2]=acc[i][2]*dv+q0.z; o[3]=acc[i][3]*dv+q0.w;
        o[4]=acc[i][4]*dv+q1.x; o[5]=acc[i][5]*dv+q1.y;
        o[6]=acc[i][6]*dv+q1.z; o[7]=acc[i][7]*dv+q1.w;
        __half hh[8], ll[8];
#pragma unroll
        for (int j = 0; j < 8; j++) {
            hh[j] = __float2half(o[j]);
            ll[j] = __float2half(o[j] - __half2float(hh[j]));
        }
        const int kcol = h*128 + tx*8;
        *(uint4*)(g_ys + mg * KSP + kcol)        = *(uint4*)hh;
        *(uint4*)(g_ys + mg * KSP + 1024 + kcol) = *(uint4*)ll;
    }
}

// ---------------------------------------------------------------------------
extern "C" void kernel_launch(void* const* d_in, const int* in_sizes, int n_in,
                              void* d_out, int out_size)
{
    const float* x  = (const float*)d_in[0];
    const float* Wq = (const float*)d_in[1];
    const float* bq = (const float*)d_in[2];
    const float* Wk = (const float*)d_in[3];
    const float* bk = (const float*)d_in[4];
    const float* Wv = (const float*)d_in[5];
    const float* bv = (const float*)d_in[6];
    const float* Wp = (const float*)d_in[7];
    const float* bp = (const float*)d_in[8];
    float* out = (float*)d_out;

    __half *pxs, *pwq, *pwk, *pwv, *pwp;
    cudaGetSymbolAddress((void**)&pxs, g_xs);
    cudaGetSymbolAddress((void**)&pwq, g_wq);
    cudaGetSymbolAddress((void**)&pwk, g_wk);
    cudaGetSymbolAddress((void**)&pwv, g_wv);
    cudaGetSymbolAddress((void**)&pwp, g_wp);

    cudaFuncSetAttribute(qkv_gemm_kernel,  cudaFuncAttributeMaxDynamicSharedMemorySize, GEMM_SMEM);
    cudaFuncSetAttribute(proj_gemm_kernel, cudaFuncAttributeMaxDynamicSharedMemorySize, GEMM_SMEM);

    zero_kernel<<<2048, 256>>>();

    convert_a_kernel<<<Mq*Cq/4/256, 256>>>(x, pxs);
    convert_w_kernel<<<dim3(32,32), 256>>>(Wq, pwq);
    convert_w_kernel<<<dim3(32,32), 256>>>(Wk, pwk);
    convert_w_kernel<<<dim3(32,32), 256>>>(Wv, pwv);
    convert_w_kernel<<<dim3(32,32), 256>>>(Wp, pwp);

    // QKV with fused softmax (q,k) + fused ksum (k)
    qkv_gemm_kernel<<<dim3(24, Mq/128), 256, GEMM_SMEM>>>(bq, bk, bv);

    dinv_kernel<<<ROWSq/8, 256>>>();
    ctx_kernel<<<dim3(BHq, 16), 256>>>();
    y_kernel<<<dim3(BHq, Tq/128), 256>>>();   // writes fp16 split into g_ys

    proj_gemm_kernel<<<dim3(8, Mq/128), 256, GEMM_SMEM>>>(bp, out);
}

// round 6
// speedup vs baseline: 3.7407x; 1.1499x over previous
#include <cuda_runtime.h>
#include <cuda_fp16.h>
#include <cstdint>

// Problem constants
#define Bq    4
#define Tq    8192
#define Cq    1024
#define Hq    8
#define Dq    128
#define Mq    (Bq*Tq)          // 32768
#define BHq   (Bq*Hq)          // 32
#define ROWSq (Mq*Hq)          // 262144
#define KSP   2048             // fp16 2-term split K'

// ---------------- device scratch ----------------
__device__ __half g_xs[(long)Mq*KSP];   // x split [m][k']   128MB
__device__ __half g_ys[(long)Mq*KSP];   // y split [m][k']   128MB
__device__ __half g_wq[1024*KSP];
__device__ __half g_wk[1024*KSP];
__device__ __half g_wv[1024*KSP];
__device__ __half g_wp[1024*KSP];
__device__ float  g_q  [(long)Mq*Cq];   // fp32 q (softmaxed) for residual + dinv
__device__ __half g_q16[(long)Mq*Cq];   // fp16 copies for MMA
__device__ __half g_k16[(long)Mq*Cq];
__device__ __half g_v16[(long)Mq*Cq];
__device__ float g_ctx[BHq*Dq*Dq];
__device__ float g_ksum[BHq*Dq];
__device__ float g_dinv[BHq*Tq];

// ---------------- PTX helpers ----------------
__device__ __forceinline__ uint32_t smem_to_u32(const void* p) {
    uint32_t a;
    asm("{ .reg .u64 t; cvta.to.shared.u64 t, %1; cvt.u32.u64 %0, t; }" : "=r"(a) : "l"(p));
    return a;
}
#define CP_ASYNC16(dst, src) \
    asm volatile("cp.async.cg.shared.global [%0], [%1], 16;" :: "r"(dst), "l"(src))
#define CP_COMMIT() asm volatile("cp.async.commit_group;" ::: "memory")
#define CP_WAIT(n)  asm volatile("cp.async.wait_group %0;" :: "n"(n) : "memory")

__device__ __forceinline__ void ldm_x4(uint32_t& r0, uint32_t& r1, uint32_t& r2, uint32_t& r3,
                                       uint32_t a) {
    asm volatile("ldmatrix.sync.aligned.m8n8.x4.shared.b16 {%0,%1,%2,%3}, [%4];"
                 : "=r"(r0), "=r"(r1), "=r"(r2), "=r"(r3) : "r"(a));
}
__device__ __forceinline__ void ldm_x4t(uint32_t& r0, uint32_t& r1, uint32_t& r2, uint32_t& r3,
                                        uint32_t a) {
    asm volatile("ldmatrix.sync.aligned.m8n8.x4.trans.shared.b16 {%0,%1,%2,%3}, [%4];"
                 : "=r"(r0), "=r"(r1), "=r"(r2), "=r"(r3) : "r"(a));
}
__device__ __forceinline__ void mma16816(float* c, uint32_t a0, uint32_t a1, uint32_t a2,
                                         uint32_t a3, uint32_t b0, uint32_t b1) {
    asm volatile(
        "mma.sync.aligned.m16n8k16.row.col.f32.f16.f16.f32 "
        "{%0,%1,%2,%3}, {%4,%5,%6,%7}, {%8,%9}, {%0,%1,%2,%3};"
        : "+f"(c[0]), "+f"(c[1]), "+f"(c[2]), "+f"(c[3])
        : "r"(a0), "r"(a1), "r"(a2), "r"(a3), "r"(b0), "r"(b1));
}

// ---------------- big-GEMM tiling ----------------
#define BKq   64
#define AST   72
#define ASTB  144
#define TILEB (128*ASTB)
#define NKCH  (KSP/BKq)          // 32
#define GEMM_SMEM (4*TILEB)      // 73728

__device__ __forceinline__ void load_tile(uint32_t sdst, const __half* g, int tid) {
#pragma unroll
    for (int i = 0; i < 4; i++) {
        int idx = tid + i * 256;
        int row = idx >> 3, seg = idx & 7;
        CP_ASYNC16(sdst + row * ASTB + seg * 16,
                   (const char*)(g + (long)row * KSP) + seg * 16);
    }
}

// modes: 0 = v (fp16 store), 1 = q (softmax; fp32+fp16 store), 2 = k (softmax; fp16 + ksum),
//        3 = plain fp32 store (final projection)
__device__ void gemm128(const __half* __restrict__ A,
                        const __half* __restrict__ Bw,
                        const float* __restrict__ bias, float* __restrict__ C,
                        __half* __restrict__ C16,
                        int m0, int n0, int mode)
{
    extern __shared__ char smem[];
    const uint32_t sb = smem_to_u32(smem);
    const int tid = threadIdx.x, lane = tid & 31, wid = tid >> 5;
    const int wm = wid & 1;
    const int wn = wid >> 1;

    float acc[4][4][4];
#pragma unroll
    for (int i = 0; i < 4; i++)
#pragma unroll
        for (int j = 0; j < 4; j++)
#pragma unroll
            for (int r = 0; r < 4; r++) acc[i][j][r] = 0.f;

    const uint32_t aB[2] = { sb,           sb + TILEB   };
    const uint32_t bB[2] = { sb + 2*TILEB, sb + 3*TILEB };
    const __half* Ab = A + (long)m0 * KSP;
    const __half* Bb = Bw + (long)n0 * KSP;

    load_tile(aB[0], Ab, tid);
    load_tile(bB[0], Bb, tid);
    CP_COMMIT();

    const uint32_t aoff = (uint32_t)((wm*64 + (lane & 7) + ((lane >> 3) & 1) * 8) * ASTB
                                     + ((lane >> 4) * 8) * 2);
    const uint32_t boff = (uint32_t)((wn*32 + (lane & 7) + (lane >> 4) * 8) * ASTB
                                     + (((lane >> 3) & 1) * 8) * 2);

    for (int c = 0; c < NKCH; c++) {
        const int buf = c & 1;
        if (c + 1 < NKCH) {
            load_tile(aB[buf ^ 1], Ab + (c + 1) * BKq, tid);
            load_tile(bB[buf ^ 1], Bb + (c + 1) * BKq, tid);
            CP_COMMIT();
            CP_WAIT(1);
        } else {
            CP_WAIT(0);
        }
        __syncthreads();

#pragma unroll
        for (int kk = 0; kk < 4; kk++) {
            uint32_t a[4][4], b[2][4];
#pragma unroll
            for (int mi = 0; mi < 4; mi++)
                ldm_x4(a[mi][0], a[mi][1], a[mi][2], a[mi][3],
                       aB[buf] + aoff + mi * 16 * ASTB + kk * 32);
#pragma unroll
            for (int nf = 0; nf < 2; nf++)
                ldm_x4(b[nf][0], b[nf][1], b[nf][2], b[nf][3],
                       bB[buf] + boff + nf * 16 * ASTB + kk * 32);
#pragma unroll
            for (int mi = 0; mi < 4; mi++)
#pragma unroll
                for (int ni = 0; ni < 4; ni++)
                    mma16816(acc[mi][ni], a[mi][0], a[mi][1], a[mi][2], a[mi][3],
                             b[ni >> 1][(ni & 1) * 2], b[ni >> 1][(ni & 1) * 2 + 1]);
        }
        __syncthreads();
    }

    // ----- epilogue -----
    const int rb = wm * 64 + (lane >> 2);
    const int cb = wn * 32 + (lane & 3) * 2;

#pragma unroll
    for (int ni = 0; ni < 4; ni++) {
        float bx = bias[n0 + cb + ni*8];
        float by = bias[n0 + cb + ni*8 + 1];
#pragma unroll
        for (int mi = 0; mi < 4; mi++) {
            acc[mi][ni][0] += bx; acc[mi][ni][1] += by;
            acc[mi][ni][2] += bx; acc[mi][ni][3] += by;
        }
    }

    if (mode == 1 || mode == 2) {
        float* red = (float*)smem;
        float rm[4][2];
#pragma unroll
        for (int mi = 0; mi < 4; mi++) {
            float m0v = -1e30f, m1v = -1e30f;
#pragma unroll
            for (int ni = 0; ni < 4; ni++) {
                m0v = fmaxf(m0v, fmaxf(acc[mi][ni][0], acc[mi][ni][1]));
                m1v = fmaxf(m1v, fmaxf(acc[mi][ni][2], acc[mi][ni][3]));
            }
            m0v = fmaxf(m0v, __shfl_xor_sync(~0u, m0v, 1));
            m0v = fmaxf(m0v, __shfl_xor_sync(~0u, m0v, 2));
            m1v = fmaxf(m1v, __shfl_xor_sync(~0u, m1v, 1));
            m1v = fmaxf(m1v, __shfl_xor_sync(~0u, m1v, 2));
            rm[mi][0] = m0v; rm[mi][1] = m1v;
        }
        if ((lane & 3) == 0)
#pragma unroll
            for (int mi = 0; mi < 4; mi++) {
                red[wn*128 + rb + mi*16]     = rm[mi][0];
                red[wn*128 + rb + mi*16 + 8] = rm[mi][1];
            }
        __syncthreads();
#pragma unroll
        for (int mi = 0; mi < 4; mi++) {
            int r0i = rb + mi*16;
            rm[mi][0] = fmaxf(fmaxf(red[r0i], red[128 + r0i]),
                              fmaxf(red[256 + r0i], red[384 + r0i]));
            rm[mi][1] = fmaxf(fmaxf(red[r0i+8], red[128 + r0i+8]),
                              fmaxf(red[256 + r0i+8], red[384 + r0i+8]));
        }
        __syncthreads();
        float rs[4][2];
#pragma unroll
        for (int mi = 0; mi < 4; mi++) {
            float s0 = 0.f, s1 = 0.f;
#pragma unroll
            for (int ni = 0; ni < 4; ni++) {
                acc[mi][ni][0] = __expf(acc[mi][ni][0] - rm[mi][0]); s0 += acc[mi][ni][0];
                acc[mi][ni][1] = __expf(acc[mi][ni][1] - rm[mi][0]); s0 += acc[mi][ni][1];
                acc[mi][ni][2] = __expf(acc[mi][ni][2] - rm[mi][1]); s1 += acc[mi][ni][2];
                acc[mi][ni][3] = __expf(acc[mi][ni][3] - rm[mi][1]); s1 += acc[mi][ni][3];
            }
            s0 += __shfl_xor_sync(~0u, s0, 1); s0 += __shfl_xor_sync(~0u, s0, 2);
            s1 += __shfl_xor_sync(~0u, s1, 1); s1 += __shfl_xor_sync(~0u, s1, 2);
            rs[mi][0] = s0; rs[mi][1] = s1;
        }
        if ((lane & 3) == 0)
#pragma unroll
            for (int mi = 0; mi < 4; mi++) {
                red[wn*128 + rb + mi*16]     = rs[mi][0];
                red[wn*128 + rb + mi*16 + 8] = rs[mi][1];
            }
        __syncthreads();
#pragma unroll
        for (int mi = 0; mi < 4; mi++) {
            int r0i = rb + mi*16;
            float inv0 = 1.f / (red[r0i] + red[128 + r0i] + red[256 + r0i] + red[384 + r0i]);
            float inv1 = 1.f / (red[r0i+8] + red[128 + r0i+8] + red[256 + r0i+8] + red[384 + r0i+8]);
#pragma unroll
            for (int ni = 0; ni < 4; ni++) {
                acc[mi][ni][0] *= inv0; acc[mi][ni][1] *= inv0;
                acc[mi][ni][2] *= inv1; acc[mi][ni][3] *= inv1;
            }
        }
    }

    // stores
    if (mode == 1 || mode == 3) {   // fp32 store (q or final output)
#pragma unroll
        for (int mi = 0; mi < 4; mi++)
#pragma unroll
            for (int ni = 0; ni < 4; ni++) {
                int row = rb + mi * 16, col = cb + ni * 8;
                *(float2*)(C + (long)(m0 + row) * 1024 + n0 + col) =
                    make_float2(acc[mi][ni][0], acc[mi][ni][1]);
                *(float2*)(C + (long)(m0 + row + 8) * 1024 + n0 + col) =
                    make_float2(acc[mi][ni][2], acc[mi][ni][3]);
            }
    }
    if (mode <= 2) {                 // fp16 store (q16/k16/v16)
#pragma unroll
        for (int mi = 0; mi < 4; mi++)
#pragma unroll
            for (int ni = 0; ni < 4; ni++) {
                int row = rb + mi * 16, col = cb + ni * 8;
                *(__half2*)(C16 + (long)(m0 + row) * 1024 + n0 + col) =
                    __floats2half2_rn(acc[mi][ni][0], acc[mi][ni][1]);
                *(__half2*)(C16 + (long)(m0 + row + 8) * 1024 + n0 + col) =
                    __floats2half2_rn(acc[mi][ni][2], acc[mi][ni][3]);
            }
    }

    if (mode == 2) {   // fused ksum
        float cs[8];
#pragma unroll
        for (int ni = 0; ni < 4; ni++)
#pragma unroll
            for (int p = 0; p < 2; p++) {
                float s = 0.f;
#pragma unroll
                for (int mi = 0; mi < 4; mi++)
                    s += acc[mi][ni][p] + acc[mi][ni][p + 2];
                cs[ni*2 + p] = s;
            }
#pragma unroll
        for (int j = 0; j < 8; j++) {
            cs[j] += __shfl_xor_sync(~0u, cs[j], 4);
            cs[j] += __shfl_xor_sync(~0u, cs[j], 8);
            cs[j] += __shfl_xor_sync(~0u, cs[j], 16);
        }
        if (lane < 4) {
            const int bh = (m0 >> 13) * 8 + (n0 >> 7);
#pragma unroll
            for (int j = 0; j < 8; j++)
                atomicAdd(&g_ksum[bh*128 + cb + (j >> 1)*8 + (j & 1)], cs[j]);
        }
    }
}

__global__ __launch_bounds__(256, 2)
void qkv_gemm_kernel(const float* bq, const float* bk, const float* bv)
{
    const int sel = blockIdx.x >> 3;
    const int n0 = (blockIdx.x & 7) * 128;
    const int m0 = blockIdx.y * 128;
    const __half* W   = (sel == 0) ? g_wq : (sel == 1) ? g_wk : g_wv;
    const float* bias = (sel == 0) ? bq  : (sel == 1) ? bk  : bv;
    __half* C16       = (sel == 0) ? g_q16 : (sel == 1) ? g_k16 : g_v16;
    const int mode    = (sel == 0) ? 1 : (sel == 1) ? 2 : 0;
    gemm128(g_xs, W, bias, g_q, C16, m0, n0, mode);
}

__global__ __launch_bounds__(256, 2)
void proj_gemm_kernel(const float* bp, float* out)
{
    gemm128(g_ys, g_wp, bp, out, (__half*)0, blockIdx.y * 128, blockIdx.x * 128, 3);
}

// ---------------- conversion kernels ----------------
__global__ void convert_a_kernel(const float* __restrict__ X, __half* __restrict__ O)
{
    long gid = (long)blockIdx.x * blockDim.x + threadIdx.x;
    long i = gid * 4;
    long m = i >> 10;
    int  k = (int)(i & 1023);
    float4 v = *(const float4*)(X + i);
    __half h[4], l[4];
    float vv[4] = {v.x, v.y, v.z, v.w};
#pragma unroll
    for (int j = 0; j < 4; j++) {
        h[j] = __float2half(vv[j]);
        l[j] = __float2half(vv[j] - __half2float(h[j]));
    }
    __half* base = O + m * KSP;
    *(uint2*)(base + k)        = *(uint2*)h;
    *(uint2*)(base + 1024 + k) = *(uint2*)l;
}

__global__ void convert_w_kernel(const float* __restrict__ W, __half* __restrict__ O)
{
    __shared__ float tile[32][33];
    const int n0 = blockIdx.x * 32, k0 = blockIdx.y * 32;
    const int tx = threadIdx.x & 31, ty = threadIdx.x >> 5;
#pragma unroll
    for (int r = 0; r < 32; r += 8)
        tile[ty + r][tx] = W[(long)(k0 + ty + r) * 1024 + n0 + tx];
    __syncthreads();
#pragma unroll
    for (int r = 0; r < 32; r += 8) {
        const int n = n0 + ty + r;
        float v = tile[tx][ty + r];
        __half hi = __float2half(v);
        __half* base = O + (long)n * KSP + k0 + tx;
        base[0]    = hi;
        base[1024] = hi;
    }
}

__global__ void zero_kernel() {
    int i = blockIdx.x * blockDim.x + threadIdx.x;
    if (i < BHq*Dq*Dq) g_ctx[i] = 0.f;
    if (i < BHq*Dq)    g_ksum[i] = 0.f;
}

// ---------------- D_inv ----------------
__global__ void dinv_kernel()
{
    int gw = (blockIdx.x * blockDim.x + threadIdx.x) >> 5;
    if (gw >= ROWSq) return;
    int lane = threadIdx.x & 31;
    int h = gw & 7;
    int bt = gw >> 3;
    int t = bt & (Tq - 1);
    int b = bt >> 13;
    float4 qv = *(const float4*)(g_q + (long)gw * 128 + lane * 4);
    float4 kv = *(const float4*)(g_ksum + (b*Hq + h) * 128 + lane * 4);
    float s = qv.x*kv.x + qv.y*kv.y + qv.z*kv.z + qv.w*kv.w;
#pragma unroll
    for (int o = 16; o; o >>= 1) s += __shfl_xor_sync(~0u, s, o);
    if (!lane) g_dinv[(long)(b*Hq + h) * Tq + t] = 1.f / s;
}

// ---------------- MMA attention kernels ----------------
#define LS   136                 // smem stride in halves
#define LSB  272                 // bytes
#define CTILE (64*LSB)           // 17408 bytes (64-row fp16 tile)
#define CTX_SMEM (4*CTILE)       // 69632

// load 64x128 fp16 tile (gmem row stride 1024) into smem
__device__ __forceinline__ void load_tile64(uint32_t sdst, const __half* g, int tid) {
#pragma unroll
    for (int i = 0; i < 4; i++) {
        int idx = tid + i * 256;
        int row = idx >> 4, seg = idx & 15;
        CP_ASYNC16(sdst + row * LSB + seg * 16,
                   (const char*)(g + (long)row * 1024) + seg * 16);
    }
}

// ctx[bh][d][e] += sum_t k16[t][d] * v16[t][e]  over a 1024-t slab
__global__ __launch_bounds__(256, 2)
void ctx_mma_kernel()
{
    extern __shared__ char smem[];
    const uint32_t sb = smem_to_u32(smem);
    const int bh = blockIdx.x, b = bh >> 3, h = bh & 7;
    const long row0 = (long)b * Tq + blockIdx.y * 1024;
    const int tid = threadIdx.x, lane = tid & 31, wid = tid >> 5;
    const int wm = wid & 3;      // d-slab of 32 (2 m-tiles)
    const int wn = wid >> 2;     // e-slab of 64 (8 n-tiles)

    const __half* kg = g_k16 + row0 * 1024 + h * 128;
    const __half* vg = g_v16 + row0 * 1024 + h * 128;

    const uint32_t kB[2] = { sb,            sb + CTILE     };
    const uint32_t vB[2] = { sb + 2*CTILE,  sb + 3*CTILE   };

    float acc[2][8][4];
#pragma unroll
    for (int i = 0; i < 2; i++)
#pragma unroll
        for (int j = 0; j < 8; j++)
#pragma unroll
            for (int r = 0; r < 4; r++) acc[i][j][r] = 0.f;

    load_tile64(kB[0], kg, tid);
    load_tile64(vB[0], vg, tid);
    CP_COMMIT();

    // trans-ldmatrix offsets (row = t within chunk, col = d or e)
    const uint32_t atr = (uint32_t)(((lane >> 4) * 8 + (lane & 7)) * LSB
                                    + (wm*32 + ((lane >> 3) & 1) * 8) * 2);
    const uint32_t btr = (uint32_t)((((lane >> 3) & 1) * 8 + (lane & 7)) * LSB
                                    + (wn*64 + (lane >> 4) * 8) * 2);

    const int NC = 16;   // 1024 / 64
    for (int c = 0; c < NC; c++) {
        const int buf = c & 1;
        if (c + 1 < NC) {
            load_tile64(kB[buf ^ 1], kg + (long)(c + 1) * 64 * 1024, tid);
            load_tile64(vB[buf ^ 1], vg + (long)(c + 1) * 64 * 1024, tid);
            CP_COMMIT();
            CP_WAIT(1);
        } else {
            CP_WAIT(0);
        }
        __syncthreads();

#pragma unroll
        for (int kk = 0; kk < 4; kk++) {
            uint32_t a[2][4], bfr[4][4];
#pragma unroll
            for (int mi = 0; mi < 2; mi++)
                ldm_x4t(a[mi][0], a[mi][1], a[mi][2], a[mi][3],
                        kB[buf] + atr + kk * 16 * LSB + mi * 32);
#pragma unroll
            for (int nf = 0; nf < 4; nf++)
                ldm_x4t(bfr[nf][0], bfr[nf][1], bfr[nf][2], bfr[nf][3],
                        vB[buf] + btr + kk * 16 * LSB + nf * 32);
#pragma unroll
            for (int mi = 0; mi < 2; mi++)
#pragma unroll
                for (int ni = 0; ni < 8; ni++)
                    mma16816(acc[mi][ni], a[mi][0], a[mi][1], a[mi][2], a[mi][3],
                             bfr[ni >> 1][(ni & 1) * 2], bfr[ni >> 1][(ni & 1) * 2 + 1]);
        }
        __syncthreads();
    }

    float* cbase = g_ctx + (long)bh * Dq * Dq;
    const int rb = wm * 32 + (lane >> 2);
    const int cb = wn * 64 + (lane & 3) * 2;
#pragma unroll
    for (int mi = 0; mi < 2; mi++)
#pragma unroll
        for (int ni = 0; ni < 8; ni++) {
            int d = rb + mi * 16, e = cb + ni * 8;
            atomicAdd(&cbase[d * 128 + e],           acc[mi][ni][0]);
            atomicAdd(&cbase[d * 128 + e + 1],       acc[mi][ni][1]);
            atomicAdd(&cbase[(d + 8) * 128 + e],     acc[mi][ni][2]);
            atomicAdd(&cbase[(d + 8) * 128 + e + 1], acc[mi][ni][3]);
        }
}

// y[t][e] = (sum_d q16[t][d] * ctx[d][e]) * dinv[t] + q[t][e]  -> fp16 split g_ys
__global__ __launch_bounds__(256, 2)
void y_mma_kernel()
{
    extern __shared__ char smem[];
    const uint32_t sb = smem_to_u32(smem);
    const int bh = blockIdx.x, b = bh >> 3, h = bh & 7;
    const long row0 = (long)b * Tq + blockIdx.y * 128;
    const int tid = threadIdx.x, lane = tid & 31, wid = tid >> 5;
    const int wm = wid & 3;      // t-slab of 32
    const int wn = wid >> 2;     // e-slab of 64

    const uint32_t qS = sb;                    // 128 x LS halves
    const uint32_t cS = sb + 128 * LSB;

    // load q16 tile (128 x 128)
#pragma unroll
    for (int i = 0; i < 8; i++) {
        int idx = tid + i * 256;
        int row = idx >> 4, seg = idx & 15;
        CP_ASYNC16(qS + row * LSB + seg * 16,
                   (const char*)(g_q16 + (row0 + row) * 1024 + h * 128) + seg * 16);
    }
    CP_COMMIT();
    // ctx fp32 -> fp16 smem [d][e]
    const float* cg = g_ctx + (long)bh * Dq * Dq;
#pragma unroll
    for (int i = 0; i < 16; i++) {
        int idx = tid + i * 256;          // 4096 float4 positions
        int d = idx >> 5, e4 = (idx & 31) * 4;
        float4 v = *(const float4*)(cg + d * 128 + e4);
        *(__half2*)((char*)smem + (cS - sb) + d * LSB + e4 * 2)     = __floats2half2_rn(v.x, v.y);
        *(__half2*)((char*)smem + (cS - sb) + d * LSB + e4 * 2 + 4) = __floats2half2_rn(v.z, v.w);
    }
    CP_WAIT(0);
    __syncthreads();

    float acc[2][8][4];
#pragma unroll
    for (int i = 0; i < 2; i++)
#pragma unroll
        for (int j = 0; j < 8; j++)
#pragma unroll
            for (int r = 0; r < 4; r++) acc[i][j][r] = 0.f;

    // A: normal ldmatrix from q (row = t, col = d); B: trans from ctx (row = d, col = e)
    const uint32_t aof = (uint32_t)((wm*32 + (lane & 7) + ((lane >> 3) & 1) * 8) * LSB
                                    + ((lane >> 4) * 8) * 2);
    const uint32_t btr = (uint32_t)((((lane >> 3) & 1) * 8 + (lane & 7)) * LSB
                                    + (wn*64 + (lane >> 4) * 8) * 2);

#pragma unroll
    for (int kk = 0; kk < 8; kk++) {
        uint32_t a[2][4], bfr[4][4];
#pragma unroll
        for (int mi = 0; mi < 2; mi++)
            ldm_x4(a[mi][0], a[mi][1], a[mi][2], a[mi][3],
                   qS + aof + mi * 16 * LSB + kk * 32);
#pragma unroll
        for (int nf = 0; nf < 4; nf++)
            ldm_x4t(bfr[nf][0], bfr[nf][1], bfr[nf][2], bfr[nf][3],
                    cS + btr + kk * 16 * LSB + nf * 32);
#pragma unroll
        for (int mi = 0; mi < 2; mi++)
#pragma unroll
            for (int ni = 0; ni < 8; ni++)
                mma16816(acc[mi][ni], a[mi][0], a[mi][1], a[mi][2], a[mi][3],
                         bfr[ni >> 1][(ni & 1) * 2], bfr[ni >> 1][(ni & 1) * 2 + 1]);
    }

    // epilogue
    const int rb = wm * 32 + (lane >> 2);
    const int cb = wn * 64 + (lane & 3) * 2;
    const float* dinv = g_dinv + (long)bh * Tq + blockIdx.y * 128;
#pragma unroll
    for (int mi = 0; mi < 2; mi++) {
        int t1 = rb + mi * 16, t2 = t1 + 8;
        float dv1 = dinv[t1], dv2 = dinv[t2];
        long m1 = row0 + t1, m2 = row0 + t2;
#pragma unroll
        for (int ni = 0; ni < 8; ni++) {
            int e = cb + ni * 8;
            float2 q1 = *(const float2*)(g_q + m1 * 1024 + h*128 + e);
            float2 q2 = *(const float2*)(g_q + m2 * 1024 + h*128 + e);
            float o0 = acc[mi][ni][0] * dv1 + q1.x;
            float o1 = acc[mi][ni][1] * dv1 + q1.y;
            float o2 = acc[mi][ni][2] * dv2 + q2.x;
            float o3 = acc[mi][ni][3] * dv2 + q2.y;
            __half h0 = __float2half(o0), h1 = __float2half(o1);
            __half h2 = __float2half(o2), h3 = __float2half(o3);
            __half l0 = __float2half(o0 - __half2float(h0));
            __half l1 = __float2half(o1 - __half2float(h1));
            __half l2 = __float2half(o2 - __half2float(h2));
            __half l3 = __float2half(o3 - __half2float(h3));
            int kc = h*128 + e;
            *(__half2*)(g_ys + m1 * KSP + kc)        = __halves2half2(h0, h1);
            *(__half2*)(g_ys + m1 * KSP + 1024 + kc) = __halves2half2(l0, l1);
            *(__half2*)(g_ys + m2 * KSP + kc)        = __halves2half2(h2, h3);
            *(__half2*)(g_ys + m2 * KSP + 1024 + kc) = __halves2half2(l2, l3);
        }
    }
}

// ---------------------------------------------------------------------------
extern "C" void kernel_launch(void* const* d_in, const int* in_sizes, int n_in,
                              void* d_out, int out_size)
{
    const float* x  = (const float*)d_in[0];
    const float* Wq = (const float*)d_in[1];
    const float* bq = (const float*)d_in[2];
    const float* Wk = (const float*)d_in[3];
    const float* bk = (const float*)d_in[4];
    const float* Wv = (const float*)d_in[5];
    const float* bv = (const float*)d_in[6];
    const float* Wp = (const float*)d_in[7];
    const float* bp = (const float*)d_in[8];
    float* out = (float*)d_out;

    __half *pxs, *pwq, *pwk, *pwv, *pwp;
    cudaGetSymbolAddress((void**)&pxs, g_xs);
    cudaGetSymbolAddress((void**)&pwq, g_wq);
    cudaGetSymbolAddress((void**)&pwk, g_wk);
    cudaGetSymbolAddress((void**)&pwv, g_wv);
    cudaGetSymbolAddress((void**)&pwp, g_wp);

    cudaFuncSetAttribute(qkv_gemm_kernel,  cudaFuncAttributeMaxDynamicSharedMemorySize, GEMM_SMEM);
    cudaFuncSetAttribute(proj_gemm_kernel, cudaFuncAttributeMaxDynamicSharedMemorySize, GEMM_SMEM);
    cudaFuncSetAttribute(ctx_mma_kernel,   cudaFuncAttributeMaxDynamicSharedMemorySize, CTX_SMEM);
    cudaFuncSetAttribute(y_mma_kernel,     cudaFuncAttributeMaxDynamicSharedMemorySize, CTX_SMEM);

    zero_kernel<<<2048, 256>>>();

    convert_a_kernel<<<Mq*Cq/4/256, 256>>>(x, pxs);
    convert_w_kernel<<<dim3(32,32), 256>>>(Wq, pwq);
    convert_w_kernel<<<dim3(32,32), 256>>>(Wk, pwk);
    convert_w_kernel<<<dim3(32,32), 256>>>(Wv, pwv);
    convert_w_kernel<<<dim3(32,32), 256>>>(Wp, pwp);

    qkv_gemm_kernel<<<dim3(24, Mq/128), 256, GEMM_SMEM>>>(bq, bk, bv);

    dinv_kernel<<<ROWSq/8, 256>>>();
    ctx_mma_kernel<<<dim3(BHq, 8), 256, CTX_SMEM>>>();
    y_mma_kernel<<<dim3(BHq, Tq/128), 256, CTX_SMEM>>>();

    proj_gemm_kernel<<<dim3(8, Mq/128), 256, GEMM_SMEM>>>(bp, out);
}

// round 7
// speedup vs baseline: 6.3649x; 1.7015x over previous
#include <cuda_runtime.h>
#include <cuda_fp16.h>
#include <cstdint>

// Problem constants
#define Bq    4
#define Tq    8192
#define Cq    1024
#define Hq    8
#define Dq    128
#define Mq    (Bq*Tq)          // 32768
#define BHq   (Bq*Hq)          // 32
#define ROWSq (Mq*Hq)          // 262144
#define KSP   1024             // pure fp16, no split

// ---------------- device scratch ----------------
__device__ __half g_xs[(long)Mq*KSP];   // x fp16 [m][k]   64MB
__device__ __half g_ys[(long)Mq*KSP];   // y fp16 [m][k]   64MB
__device__ __half g_wq[1024*KSP];       // W^T fp16 [n][k]  2MB
__device__ __half g_wk[1024*KSP];
__device__ __half g_wv[1024*KSP];
__device__ __half g_wp[1024*KSP];
__device__ float  g_q  [(long)Mq*Cq];   // fp32 q (softmaxed) for residual + dinv
__device__ __half g_q16[(long)Mq*Cq];   // fp16 copies for MMA
__device__ __half g_k16[(long)Mq*Cq];
__device__ __half g_v16[(long)Mq*Cq];
__device__ float g_ctx[BHq*Dq*Dq];
__device__ float g_ksum[BHq*Dq];
__device__ float g_dinv[BHq*Tq];

// ---------------- PTX helpers ----------------
__device__ __forceinline__ uint32_t smem_to_u32(const void* p) {
    uint32_t a;
    asm("{ .reg .u64 t; cvta.to.shared.u64 t, %1; cvt.u32.u64 %0, t; }" : "=r"(a) : "l"(p));
    return a;
}
#define CP_ASYNC16(dst, src) \
    asm volatile("cp.async.cg.shared.global [%0], [%1], 16;" :: "r"(dst), "l"(src))
#define CP_COMMIT() asm volatile("cp.async.commit_group;" ::: "memory")
#define CP_WAIT(n)  asm volatile("cp.async.wait_group %0;" :: "n"(n) : "memory")

__device__ __forceinline__ void ldm_x4(uint32_t& r0, uint32_t& r1, uint32_t& r2, uint32_t& r3,
                                       uint32_t a) {
    asm volatile("ldmatrix.sync.aligned.m8n8.x4.shared.b16 {%0,%1,%2,%3}, [%4];"
                 : "=r"(r0), "=r"(r1), "=r"(r2), "=r"(r3) : "r"(a));
}
__device__ __forceinline__ void ldm_x4t(uint32_t& r0, uint32_t& r1, uint32_t& r2, uint32_t& r3,
                                        uint32_t a) {
    asm volatile("ldmatrix.sync.aligned.m8n8.x4.trans.shared.b16 {%0,%1,%2,%3}, [%4];"
                 : "=r"(r0), "=r"(r1), "=r"(r2), "=r"(r3) : "r"(a));
}
__device__ __forceinline__ void mma16816(float* c, uint32_t a0, uint32_t a1, uint32_t a2,
                                         uint32_t a3, uint32_t b0, uint32_t b1) {
    asm volatile(
        "mma.sync.aligned.m16n8k16.row.col.f32.f16.f16.f32 "
        "{%0,%1,%2,%3}, {%4,%5,%6,%7}, {%8,%9}, {%0,%1,%2,%3};"
        : "+f"(c[0]), "+f"(c[1]), "+f"(c[2]), "+f"(c[3])
        : "r"(a0), "r"(a1), "r"(a2), "r"(a3), "r"(b0), "r"(b1));
}

// ---------------- big-GEMM tiling ----------------
#define BKq   64
#define AST   72
#define ASTB  144
#define TILEB (128*ASTB)
#define NKCH  (KSP/BKq)          // 16
#define GEMM_SMEM (4*TILEB)      // 73728

__device__ __forceinline__ void load_tile(uint32_t sdst, const __half* g, int tid) {
#pragma unroll
    for (int i = 0; i < 4; i++) {
        int idx = tid + i * 256;
        int row = idx >> 3, seg = idx & 7;
        CP_ASYNC16(sdst + row * ASTB + seg * 16,
                   (const char*)(g + (long)row * KSP) + seg * 16);
    }
}

// modes: 0 = v (fp16 store), 1 = q (softmax; fp32+fp16 store), 2 = k (softmax; fp16 + ksum),
//        3 = plain fp32 store (final projection)
__device__ void gemm128(const __half* __restrict__ A,
                        const __half* __restrict__ Bw,
                        const float* __restrict__ bias, float* __restrict__ C,
                        __half* __restrict__ C16,
                        int m0, int n0, int mode)
{
    extern __shared__ char smem[];
    const uint32_t sb = smem_to_u32(smem);
    const int tid = threadIdx.x, lane = tid & 31, wid = tid >> 5;
    const int wm = wid & 1;
    const int wn = wid >> 1;

    float acc[4][4][4];
#pragma unroll
    for (int i = 0; i < 4; i++)
#pragma unroll
        for (int j = 0; j < 4; j++)
#pragma unroll
            for (int r = 0; r < 4; r++) acc[i][j][r] = 0.f;

    const uint32_t aB[2] = { sb,           sb + TILEB   };
    const uint32_t bB[2] = { sb + 2*TILEB, sb + 3*TILEB };
    const __half* Ab = A + (long)m0 * KSP;
    const __half* Bb = Bw + (long)n0 * KSP;

    load_tile(aB[0], Ab, tid);
    load_tile(bB[0], Bb, tid);
    CP_COMMIT();

    const uint32_t aoff = (uint32_t)((wm*64 + (lane & 7) + ((lane >> 3) & 1) * 8) * ASTB
                                     + ((lane >> 4) * 8) * 2);
    const uint32_t boff = (uint32_t)((wn*32 + (lane & 7) + (lane >> 4) * 8) * ASTB
                                     + (((lane >> 3) & 1) * 8) * 2);

    for (int c = 0; c < NKCH; c++) {
        const int buf = c & 1;
        if (c + 1 < NKCH) {
            load_tile(aB[buf ^ 1], Ab + (c + 1) * BKq, tid);
            load_tile(bB[buf ^ 1], Bb + (c + 1) * BKq, tid);
            CP_COMMIT();
            CP_WAIT(1);
        } else {
            CP_WAIT(0);
        }
        __syncthreads();

#pragma unroll
        for (int kk = 0; kk < 4; kk++) {
            uint32_t a[4][4], b[2][4];
#pragma unroll
            for (int mi = 0; mi < 4; mi++)
                ldm_x4(a[mi][0], a[mi][1], a[mi][2], a[mi][3],
                       aB[buf] + aoff + mi * 16 * ASTB + kk * 32);
#pragma unroll
            for (int nf = 0; nf < 2; nf++)
                ldm_x4(b[nf][0], b[nf][1], b[nf][2], b[nf][3],
                       bB[buf] + boff + nf * 16 * ASTB + kk * 32);
#pragma unroll
            for (int mi = 0; mi < 4; mi++)
#pragma unroll
                for (int ni = 0; ni < 4; ni++)
                    mma16816(acc[mi][ni], a[mi][0], a[mi][1], a[mi][2], a[mi][3],
                             b[ni >> 1][(ni & 1) * 2], b[ni >> 1][(ni & 1) * 2 + 1]);
        }
        __syncthreads();
    }

    // ----- epilogue -----
    const int rb = wm * 64 + (lane >> 2);
    const int cb = wn * 32 + (lane & 3) * 2;

#pragma unroll
    for (int ni = 0; ni < 4; ni++) {
        float bx = bias[n0 + cb + ni*8];
        float by = bias[n0 + cb + ni*8 + 1];
#pragma unroll
        for (int mi = 0; mi < 4; mi++) {
            acc[mi][ni][0] += bx; acc[mi][ni][1] += by;
            acc[mi][ni][2] += bx; acc[mi][ni][3] += by;
        }
    }

    if (mode == 1 || mode == 2) {
        float* red = (float*)smem;
        float rm[4][2];
#pragma unroll
        for (int mi = 0; mi < 4; mi++) {
            float m0v = -1e30f, m1v = -1e30f;
#pragma unroll
            for (int ni = 0; ni < 4; ni++) {
                m0v = fmaxf(m0v, fmaxf(acc[mi][ni][0], acc[mi][ni][1]));
                m1v = fmaxf(m1v, fmaxf(acc[mi][ni][2], acc[mi][ni][3]));
            }
            m0v = fmaxf(m0v, __shfl_xor_sync(~0u, m0v, 1));
            m0v = fmaxf(m0v, __shfl_xor_sync(~0u, m0v, 2));
            m1v = fmaxf(m1v, __shfl_xor_sync(~0u, m1v, 1));
            m1v = fmaxf(m1v, __shfl_xor_sync(~0u, m1v, 2));
            rm[mi][0] = m0v; rm[mi][1] = m1v;
        }
        if ((lane & 3) == 0)
#pragma unroll
            for (int mi = 0; mi < 4; mi++) {
                red[wn*128 + rb + mi*16]     = rm[mi][0];
                red[wn*128 + rb + mi*16 + 8] = rm[mi][1];
            }
        __syncthreads();
#pragma unroll
        for (int mi = 0; mi < 4; mi++) {
            int r0i = rb + mi*16;
            rm[mi][0] = fmaxf(fmaxf(red[r0i], red[128 + r0i]),
                              fmaxf(red[256 + r0i], red[384 + r0i]));
            rm[mi][1] = fmaxf(fmaxf(red[r0i+8], red[128 + r0i+8]),
                              fmaxf(red[256 + r0i+8], red[384 + r0i+8]));
        }
        __syncthreads();
        float rs[4][2];
#pragma unroll
        for (int mi = 0; mi < 4; mi++) {
            float s0 = 0.f, s1 = 0.f;
#pragma unroll
            for (int ni = 0; ni < 4; ni++) {
                acc[mi][ni][0] = __expf(acc[mi][ni][0] - rm[mi][0]); s0 += acc[mi][ni][0];
                acc[mi][ni][1] = __expf(acc[mi][ni][1] - rm[mi][0]); s0 += acc[mi][ni][1];
                acc[mi][ni][2] = __expf(acc[mi][ni][2] - rm[mi][1]); s1 += acc[mi][ni][2];
                acc[mi][ni][3] = __expf(acc[mi][ni][3] - rm[mi][1]); s1 += acc[mi][ni][3];
            }
            s0 += __shfl_xor_sync(~0u, s0, 1); s0 += __shfl_xor_sync(~0u, s0, 2);
            s1 += __shfl_xor_sync(~0u, s1, 1); s1 += __shfl_xor_sync(~0u, s1, 2);
            rs[mi][0] = s0; rs[mi][1] = s1;
        }
        if ((lane & 3) == 0)
#pragma unroll
            for (int mi = 0; mi < 4; mi++) {
                red[wn*128 + rb + mi*16]     = rs[mi][0];
                red[wn*128 + rb + mi*16 + 8] = rs[mi][1];
            }
        __syncthreads();
#pragma unroll
        for (int mi = 0; mi < 4; mi++) {
            int r0i = rb + mi*16;
            float inv0 = 1.f / (red[r0i] + red[128 + r0i] + red[256 + r0i] + red[384 + r0i]);
            float inv1 = 1.f / (red[r0i+8] + red[128 + r0i+8] + red[256 + r0i+8] + red[384 + r0i+8]);
#pragma unroll
            for (int ni = 0; ni < 4; ni++) {
                acc[mi][ni][0] *= inv0; acc[mi][ni][1] *= inv0;
                acc[mi][ni][2] *= inv1; acc[mi][ni][3] *= inv1;
            }
        }
    }

    // stores
    if (mode == 1 || mode == 3) {
#pragma unroll
        for (int mi = 0; mi < 4; mi++)
#pragma unroll
            for (int ni = 0; ni < 4; ni++) {
                int row = rb + mi * 16, col = cb + ni * 8;
                *(float2*)(C + (long)(m0 + row) * 1024 + n0 + col) =
                    make_float2(acc[mi][ni][0], acc[mi][ni][1]);
                *(float2*)(C + (long)(m0 + row + 8) * 1024 + n0 + col) =
                    make_float2(acc[mi][ni][2], acc[mi][ni][3]);
            }
    }
    if (mode <= 2) {
#pragma unroll
        for (int mi = 0; mi < 4; mi++)
#pragma unroll
            for (int ni = 0; ni < 4; ni++) {
                int row = rb + mi * 16, col = cb + ni * 8;
                *(__half2*)(C16 + (long)(m0 + row) * 1024 + n0 + col) =
                    __floats2half2_rn(acc[mi][ni][0], acc[mi][ni][1]);
                *(__half2*)(C16 + (long)(m0 + row + 8) * 1024 + n0 + col) =
                    __floats2half2_rn(acc[mi][ni][2], acc[mi][ni][3]);
            }
    }

    if (mode == 2) {   // fused ksum
        float cs[8];
#pragma unroll
        for (int ni = 0; ni < 4; ni++)
#pragma unroll
            for (int p = 0; p < 2; p++) {
                float s = 0.f;
#pragma unroll
                for (int mi = 0; mi < 4; mi++)
                    s += acc[mi][ni][p] + acc[mi][ni][p + 2];
                cs[ni*2 + p] = s;
            }
#pragma unroll
        for (int j = 0; j < 8; j++) {
            cs[j] += __shfl_xor_sync(~0u, cs[j], 4);
            cs[j] += __shfl_xor_sync(~0u, cs[j], 8);
            cs[j] += __shfl_xor_sync(~0u, cs[j], 16);
        }
        if (lane < 4) {
            const int bh = (m0 >> 13) * 8 + (n0 >> 7);
#pragma unroll
            for (int j = 0; j < 8; j++)
                atomicAdd(&g_ksum[bh*128 + cb + (j >> 1)*8 + (j & 1)], cs[j]);
        }
    }
}

__global__ __launch_bounds__(256, 2)
void qkv_gemm_kernel(const float* bq, const float* bk, const float* bv)
{
    const int sel = blockIdx.x >> 3;
    const int n0 = (blockIdx.x & 7) * 128;
    const int m0 = blockIdx.y * 128;
    const __half* W   = (sel == 0) ? g_wq : (sel == 1) ? g_wk : g_wv;
    const float* bias = (sel == 0) ? bq  : (sel == 1) ? bk  : bv;
    __half* C16       = (sel == 0) ? g_q16 : (sel == 1) ? g_k16 : g_v16;
    const int mode    = (sel == 0) ? 1 : (sel == 1) ? 2 : 0;
    gemm128(g_xs, W, bias, g_q, C16, m0, n0, mode);
}

__global__ __launch_bounds__(256, 2)
void proj_gemm_kernel(const float* bp, float* out)
{
    gemm128(g_ys, g_wp, bp, out, (__half*)0, blockIdx.y * 128, blockIdx.x * 128, 3);
}

// ---------------- conversion kernels ----------------
__global__ void convert_a_kernel(const float* __restrict__ X, __half* __restrict__ O)
{
    long i = ((long)blockIdx.x * blockDim.x + threadIdx.x) * 4;
    float4 v = *(const float4*)(X + i);
    __half h[4] = { __float2half(v.x), __float2half(v.y),
                    __float2half(v.z), __float2half(v.w) };
    *(uint2*)(O + i) = *(uint2*)h;
}

// W [K=1024][N=1024] -> O [n][k] transposed fp16
__global__ void convert_w_kernel(const float* __restrict__ W, __half* __restrict__ O)
{
    __shared__ float tile[32][33];
    const int n0 = blockIdx.x * 32, k0 = blockIdx.y * 32;
    const int tx = threadIdx.x & 31, ty = threadIdx.x >> 5;
#pragma unroll
    for (int r = 0; r < 32; r += 8)
        tile[ty + r][tx] = W[(long)(k0 + ty + r) * 1024 + n0 + tx];
    __syncthreads();
#pragma unroll
    for (int r = 0; r < 32; r += 8) {
        const int n = n0 + ty + r;
        O[(long)n * KSP + k0 + tx] = __float2half(tile[tx][ty + r]);
    }
}

__global__ void zero_kernel() {
    int i = blockIdx.x * blockDim.x + threadIdx.x;
    if (i < BHq*Dq*Dq) g_ctx[i] = 0.f;
    if (i < BHq*Dq)    g_ksum[i] = 0.f;
}

// ---------------- D_inv ----------------
__global__ void dinv_kernel()
{
    int gw = (blockIdx.x * blockDim.x + threadIdx.x) >> 5;
    if (gw >= ROWSq) return;
    int lane = threadIdx.x & 31;
    int h = gw & 7;
    int bt = gw >> 3;
    int t = bt & (Tq - 1);
    int b = bt >> 13;
    float4 qv = *(const float4*)(g_q + (long)gw * 128 + lane * 4);
    float4 kv = *(const float4*)(g_ksum + (b*Hq + h) * 128 + lane * 4);
    float s = qv.x*kv.x + qv.y*kv.y + qv.z*kv.z + qv.w*kv.w;
#pragma unroll
    for (int o = 16; o; o >>= 1) s += __shfl_xor_sync(~0u, s, o);
    if (!lane) g_dinv[(long)(b*Hq + h) * Tq + t] = 1.f / s;
}

// ---------------- MMA attention kernels ----------------
#define LS   136
#define LSB  272
#define CTILE (64*LSB)
#define CTX_SMEM (4*CTILE)

__device__ __forceinline__ void load_tile64(uint32_t sdst, const __half* g, int tid) {
#pragma unroll
    for (int i = 0; i < 4; i++) {
        int idx = tid + i * 256;
        int row = idx >> 4, seg = idx & 15;
        CP_ASYNC16(sdst + row * LSB + seg * 16,
                   (const char*)(g + (long)row * 1024) + seg * 16);
    }
}

// ctx[bh][d][e] += sum_t k16[t][d] * v16[t][e]
__global__ __launch_bounds__(256, 2)
void ctx_mma_kernel()
{
    extern __shared__ char smem[];
    const uint32_t sb = smem_to_u32(smem);
    const int bh = blockIdx.x, b = bh >> 3, h = bh & 7;
    const long row0 = (long)b * Tq + blockIdx.y * 1024;
    const int tid = threadIdx.x, lane = tid & 31, wid = tid >> 5;
    const int wm = wid & 3;
    const int wn = wid >> 2;

    const __half* kg = g_k16 + row0 * 1024 + h * 128;
    const __half* vg = g_v16 + row0 * 1024 + h * 128;

    const uint32_t kB[2] = { sb,            sb + CTILE     };
    const uint32_t vB[2] = { sb + 2*CTILE,  sb + 3*CTILE   };

    float acc[2][8][4];
#pragma unroll
    for (int i = 0; i < 2; i++)
#pragma unroll
        for (int j = 0; j < 8; j++)
#pragma unroll
            for (int r = 0; r < 4; r++) acc[i][j][r] = 0.f;

    load_tile64(kB[0], kg, tid);
    load_tile64(vB[0], vg, tid);
    CP_COMMIT();

    const uint32_t atr = (uint32_t)(((lane >> 4) * 8 + (lane & 7)) * LSB
                                    + (wm*32 + ((lane >> 3) & 1) * 8) * 2);
    const uint32_t btr = (uint32_t)((((lane >> 3) & 1) * 8 + (lane & 7)) * LSB
                                    + (wn*64 + (lane >> 4) * 8) * 2);

    const int NC = 16;
    for (int c = 0; c < NC; c++) {
        const int buf = c & 1;
        if (c + 1 < NC) {
            load_tile64(kB[buf ^ 1], kg + (long)(c + 1) * 64 * 1024, tid);
            load_tile64(vB[buf ^ 1], vg + (long)(c + 1) * 64 * 1024, tid);
            CP_COMMIT();
            CP_WAIT(1);
        } else {
            CP_WAIT(0);
        }
        __syncthreads();

#pragma unroll
        for (int kk = 0; kk < 4; kk++) {
            uint32_t a[2][4], bfr[4][4];
#pragma unroll
            for (int mi = 0; mi < 2; mi++)
                ldm_x4t(a[mi][0], a[mi][1], a[mi][2], a[mi][3],
                        kB[buf] + atr + kk * 16 * LSB + mi * 32);
#pragma unroll
            for (int nf = 0; nf < 4; nf++)
                ldm_x4t(bfr[nf][0], bfr[nf][1], bfr[nf][2], bfr[nf][3],
                        vB[buf] + btr + kk * 16 * LSB + nf * 32);
#pragma unroll
            for (int mi = 0; mi < 2; mi++)
#pragma unroll
                for (int ni = 0; ni < 8; ni++)
                    mma16816(acc[mi][ni], a[mi][0], a[mi][1], a[mi][2], a[mi][3],
                             bfr[ni >> 1][(ni & 1) * 2], bfr[ni >> 1][(ni & 1) * 2 + 1]);
        }
        __syncthreads();
    }

    float* cbase = g_ctx + (long)bh * Dq * Dq;
    const int rb = wm * 32 + (lane >> 2);
    const int cb = wn * 64 + (lane & 3) * 2;
#pragma unroll
    for (int mi = 0; mi < 2; mi++)
#pragma unroll
        for (int ni = 0; ni < 8; ni++) {
            int d = rb + mi * 16, e = cb + ni * 8;
            atomicAdd(&cbase[d * 128 + e],           acc[mi][ni][0]);
            atomicAdd(&cbase[d * 128 + e + 1],       acc[mi][ni][1]);
            atomicAdd(&cbase[(d + 8) * 128 + e],     acc[mi][ni][2]);
            atomicAdd(&cbase[(d + 8) * 128 + e + 1], acc[mi][ni][3]);
        }
}

// y[t][e] = (sum_d q16[t][d] * ctx[d][e]) * dinv[t] + q[t][e]  -> fp16 g_ys
__global__ __launch_bounds__(256, 2)
void y_mma_kernel()
{
    extern __shared__ char smem[];
    const uint32_t sb = smem_to_u32(smem);
    const int bh = blockIdx.x, b = bh >> 3, h = bh & 7;
    const long row0 = (long)b * Tq + blockIdx.y * 128;
    const int tid = threadIdx.x, lane = tid & 31, wid = tid >> 5;
    const int wm = wid & 3;
    const int wn = wid >> 2;

    const uint32_t qS = sb;
    const uint32_t cS = sb + 128 * LSB;

#pragma unroll
    for (int i = 0; i < 8; i++) {
        int idx = tid + i * 256;
        int row = idx >> 4, seg = idx & 15;
        CP_ASYNC16(qS + row * LSB + seg * 16,
                   (const char*)(g_q16 + (row0 + row) * 1024 + h * 128) + seg * 16);
    }
    CP_COMMIT();
    const float* cg = g_ctx + (long)bh * Dq * Dq;
#pragma unroll
    for (int i = 0; i < 16; i++) {
        int idx = tid + i * 256;
        int d = idx >> 5, e4 = (idx & 31) * 4;
        float4 v = *(const float4*)(cg + d * 128 + e4);
        *(__half2*)((char*)smem + (cS - sb) + d * LSB + e4 * 2)     = __floats2half2_rn(v.x, v.y);
        *(__half2*)((char*)smem + (cS - sb) + d * LSB + e4 * 2 + 4) = __floats2half2_rn(v.z, v.w);
    }
    CP_WAIT(0);
    __syncthreads();

    float acc[2][8][4];
#pragma unroll
    for (int i = 0; i < 2; i++)
#pragma unroll
        for (int j = 0; j < 8; j++)
#pragma unroll
            for (int r = 0; r < 4; r++) acc[i][j][r] = 0.f;

    const uint32_t aof = (uint32_t)((wm*32 + (lane & 7) + ((lane >> 3) & 1) * 8) * LSB
                                    + ((lane >> 4) * 8) * 2);
    const uint32_t btr = (uint32_t)((((lane >> 3) & 1) * 8 + (lane & 7)) * LSB
                                    + (wn*64 + (lane >> 4) * 8) * 2);

#pragma unroll
    for (int kk = 0; kk < 8; kk++) {
        uint32_t a[2][4], bfr[4][4];
#pragma unroll
        for (int mi = 0; mi < 2; mi++)
            ldm_x4(a[mi][0], a[mi][1], a[mi][2], a[mi][3],
                   qS + aof + mi * 16 * LSB + kk * 32);
#pragma unroll
        for (int nf = 0; nf < 4; nf++)
            ldm_x4t(bfr[nf][0], bfr[nf][1], bfr[nf][2], bfr[nf][3],
                    cS + btr + kk * 16 * LSB + nf * 32);
#pragma unroll
        for (int mi = 0; mi < 2; mi++)
#pragma unroll
            for (int ni = 0; ni < 8; ni++)
                mma16816(acc[mi][ni], a[mi][0], a[mi][1], a[mi][2], a[mi][3],
                         bfr[ni >> 1][(ni & 1) * 2], bfr[ni >> 1][(ni & 1) * 2 + 1]);
    }

    const int rb = wm * 32 + (lane >> 2);
    const int cb = wn * 64 + (lane & 3) * 2;
    const float* dinv = g_dinv + (long)bh * Tq + blockIdx.y * 128;
#pragma unroll
    for (int mi = 0; mi < 2; mi++) {
        int t1 = rb + mi * 16, t2 = t1 + 8;
        float dv1 = dinv[t1], dv2 = dinv[t2];
        long m1 = row0 + t1, m2 = row0 + t2;
#pragma unroll
        for (int ni = 0; ni < 8; ni++) {
            int e = cb + ni * 8;
            float2 q1 = *(const float2*)(g_q + m1 * 1024 + h*128 + e);
            float2 q2 = *(const float2*)(g_q + m2 * 1024 + h*128 + e);
            int kc = h*128 + e;
            *(__half2*)(g_ys + m1 * KSP + kc) =
                __floats2half2_rn(acc[mi][ni][0] * dv1 + q1.x, acc[mi][ni][1] * dv1 + q1.y);
            *(__half2*)(g_ys + m2 * KSP + kc) =
                __floats2half2_rn(acc[mi][ni][2] * dv2 + q2.x, acc[mi][ni][3] * dv2 + q2.y);
        }
    }
}

// ---------------------------------------------------------------------------
extern "C" void kernel_launch(void* const* d_in, const int* in_sizes, int n_in,
                              void* d_out, int out_size)
{
    const float* x  = (const float*)d_in[0];
    const float* Wq = (const float*)d_in[1];
    const float* bq = (const float*)d_in[2];
    const float* Wk = (const float*)d_in[3];
    const float* bk = (const float*)d_in[4];
    const float* Wv = (const float*)d_in[5];
    const float* bv = (const float*)d_in[6];
    const float* Wp = (const float*)d_in[7];
    const float* bp = (const float*)d_in[8];
    float* out = (float*)d_out;

    __half *pxs, *pwq, *pwk, *pwv, *pwp;
    cudaGetSymbolAddress((void**)&pxs, g_xs);
    cudaGetSymbolAddress((void**)&pwq, g_wq);
    cudaGetSymbolAddress((void**)&pwk, g_wk);
    cudaGetSymbolAddress((void**)&pwv, g_wv);
    cudaGetSymbolAddress((void**)&pwp, g_wp);

    cudaFuncSetAttribute(qkv_gemm_kernel,  cudaFuncAttributeMaxDynamicSharedMemorySize, GEMM_SMEM);
    cudaFuncSetAttribute(proj_gemm_kernel, cudaFuncAttributeMaxDynamicSharedMemorySize, GEMM_SMEM);
    cudaFuncSetAttribute(ctx_mma_kernel,   cudaFuncAttributeMaxDynamicSharedMemorySize, CTX_SMEM);
    cudaFuncSetAttribute(y_mma_kernel,     cudaFuncAttributeMaxDynamicSharedMemorySize, CTX_SMEM);

    zero_kernel<<<2048, 256>>>();

    convert_a_kernel<<<Mq*Cq/4/256, 256>>>(x, pxs);
    convert_w_kernel<<<dim3(32,32), 256>>>(Wq, pwq);
    convert_w_kernel<<<dim3(32,32), 256>>>(Wk, pwk);
    convert_w_kernel<<<dim3(32,32), 256>>>(Wv, pwv);
    convert_w_kernel<<<dim3(32,32), 256>>>(Wp, pwp);

    qkv_gemm_kernel<<<dim3(24, Mq/128), 256, GEMM_SMEM>>>(bq, bk, bv);

    dinv_kernel<<<ROWSq/8, 256>>>();
    ctx_mma_kernel<<<dim3(BHq, 8), 256, CTX_SMEM>>>();
    y_mma_kernel<<<dim3(BHq, Tq/128), 256, CTX_SMEM>>>();

    proj_gemm_kernel<<<dim3(8, Mq/128), 256, GEMM_SMEM>>>(bp, out);
}